// round 1
// baseline (speedup 1.0000x reference)
#include <cuda_runtime.h>

#define Bn 16
#define Cn 1024
#define Tn 2048
#define Dn 512
#define Sn (Tn / 2)
#define EPSf 1e-5f

// -------- scratch (static device arrays; no allocation allowed) --------
__device__ float g_q [(size_t)Bn * Dn * Tn];   // Q  (B,D,T)  64 MiB
__device__ float g_k [(size_t)Bn * Dn * Tn];   // K  (B,D,T)  64 MiB
__device__ float g_v [(size_t)Bn * Dn * Tn];   // V  (B,D,T)  64 MiB
__device__ float g_kp[(size_t)Bn * Dn * Sn];   // pooled K    32 MiB
__device__ float g_vp[(size_t)Bn * Dn * Sn];   // pooled V    32 MiB
__device__ float g_M [(size_t)Bn * Dn * Dn];   // V Kt        16 MiB
__device__ float g_o [(size_t)Bn * Dn * Tn];   // M Q / T     64 MiB
__device__ float g_y [(size_t)Bn * Cn * Tn];   // pre-BN y   128 MiB
__device__ float g_mean[Cn];
__device__ float g_istd[Cn];

// ---------------- SGEMM: C = alpha * A * op(B) + bias ------------------
// A: (M,K) row-major. TRANS_B=false: B (K,N) row-major. true: B (N,K) row-major.
// Batched over blockIdx.z with element strides sA/sB/sC (sA=0 -> shared weight).
// Requires M%128==0, N%128==0, K%8==0 (true for all shapes here).
template <bool TRANS_B>
__global__ void __launch_bounds__(256, 2) sgemm(
    const float* __restrict__ A, const float* __restrict__ Bm,
    float* __restrict__ Cm, const float* __restrict__ bias,
    int M, int N, int K, float alpha,
    size_t sA, size_t sB, size_t sC)
{
    constexpr int BM = 128, BN = 128, BK = 8, TM = 8, TN = 8;
    __shared__ float As[BK][BM];
    __shared__ float Bs[BK][BN];

    A  += (size_t)blockIdx.z * sA;
    Bm += (size_t)blockIdx.z * sB;
    Cm += (size_t)blockIdx.z * sC;

    const int brow = blockIdx.y * BM;
    const int bcol = blockIdx.x * BN;
    const int tid  = threadIdx.x;
    const int tx   = tid & 15;   // 16 col-groups
    const int ty   = tid >> 4;   // 16 row-groups

    // loaders: 128 rows x 8 cols (A and trans-B); 8 rows x 128 cols (no-trans B)
    const int lrow  = tid >> 1;         // 0..127
    const int lcol  = (tid & 1) * 4;    // 0 or 4
    const int nbrow = tid >> 5;         // 0..7
    const int nbcol = (tid & 31) * 4;   // 0..124

    float acc[TM][TN];
#pragma unroll
    for (int i = 0; i < TM; i++)
#pragma unroll
        for (int j = 0; j < TN; j++) acc[i][j] = 0.f;

    const float* Aptr = A + (size_t)(brow + lrow) * K + lcol;
    const float* Bptr = TRANS_B
        ? Bm + (size_t)(bcol + lrow) * K + lcol
        : Bm + (size_t)nbrow * N + bcol + nbcol;

    for (int k0 = 0; k0 < K; k0 += BK) {
        float4 av = *(const float4*)(Aptr + k0);
        As[lcol + 0][lrow] = av.x;
        As[lcol + 1][lrow] = av.y;
        As[lcol + 2][lrow] = av.z;
        As[lcol + 3][lrow] = av.w;
        if (TRANS_B) {
            float4 bv = *(const float4*)(Bptr + k0);
            Bs[lcol + 0][lrow] = bv.x;
            Bs[lcol + 1][lrow] = bv.y;
            Bs[lcol + 2][lrow] = bv.z;
            Bs[lcol + 3][lrow] = bv.w;
        } else {
            float4 bv = *(const float4*)(Bptr + (size_t)k0 * N);
            *(float4*)&Bs[nbrow][nbcol] = bv;
        }
        __syncthreads();
#pragma unroll
        for (int kk = 0; kk < BK; kk++) {
            float ar[TM], br[TN];
            *(float4*)&ar[0] = *(const float4*)&As[kk][ty * TM];
            *(float4*)&ar[4] = *(const float4*)&As[kk][ty * TM + 4];
            *(float4*)&br[0] = *(const float4*)&Bs[kk][tx * TN];
            *(float4*)&br[4] = *(const float4*)&Bs[kk][tx * TN + 4];
#pragma unroll
            for (int i = 0; i < TM; i++)
#pragma unroll
                for (int j = 0; j < TN; j++)
                    acc[i][j] += ar[i] * br[j];
        }
        __syncthreads();
    }

#pragma unroll
    for (int i = 0; i < TM; i++) {
        const int r = brow + ty * TM + i;
        const float bval = bias ? bias[r] : 0.f;
        float4 o0, o1;
        o0.x = alpha * acc[i][0] + bval;
        o0.y = alpha * acc[i][1] + bval;
        o0.z = alpha * acc[i][2] + bval;
        o0.w = alpha * acc[i][3] + bval;
        o1.x = alpha * acc[i][4] + bval;
        o1.y = alpha * acc[i][5] + bval;
        o1.z = alpha * acc[i][6] + bval;
        o1.w = alpha * acc[i][7] + bval;
        float* cp = Cm + (size_t)r * N + bcol + tx * TN;
        *(float4*)(cp)     = o0;
        *(float4*)(cp + 4) = o1;
    }
}

// ---------------- MaxPool1d(kernel=2) along contiguous last dim ----------
__global__ void pool2(const float* __restrict__ in, float* __restrict__ out, size_t n)
{
    size_t i = (size_t)blockIdx.x * blockDim.x + threadIdx.x;
    if (i < n) {
        float2 p = ((const float2*)in)[i];
        out[i] = fmaxf(p.x, p.y);
    }
}

// ---------------- BN batch stats: one block per channel ------------------
__global__ void bn_stats(const float* __restrict__ y,
                         float* __restrict__ mean, float* __restrict__ istd)
{
    const int c = blockIdx.x;
    float s = 0.f, s2 = 0.f;
    for (int b = 0; b < Bn; b++) {
        const float* row = y + ((size_t)b * Cn + c) * Tn;
        for (int t = threadIdx.x * 4; t < Tn; t += blockDim.x * 4) {
            float4 v = *(const float4*)(row + t);
            s  += v.x + v.y + v.z + v.w;
            s2 += v.x * v.x + v.y * v.y + v.z * v.z + v.w * v.w;
        }
    }
#pragma unroll
    for (int o = 16; o > 0; o >>= 1) {
        s  += __shfl_down_sync(0xffffffffu, s,  o);
        s2 += __shfl_down_sync(0xffffffffu, s2, o);
    }
    __shared__ float ss[32], ss2[32];
    const int lane = threadIdx.x & 31, w = threadIdx.x >> 5;
    if (lane == 0) { ss[w] = s; ss2[w] = s2; }
    __syncthreads();
    if (w == 0) {
        const int nw = blockDim.x >> 5;
        s  = lane < nw ? ss[lane]  : 0.f;
        s2 = lane < nw ? ss2[lane] : 0.f;
#pragma unroll
        for (int o = 16; o > 0; o >>= 1) {
            s  += __shfl_down_sync(0xffffffffu, s,  o);
            s2 += __shfl_down_sync(0xffffffffu, s2, o);
        }
        if (lane == 0) {
            const float n = (float)(Bn * Tn);
            const float m = s / n;
            mean[c] = m;
            istd[c] = rsqrtf(s2 / n - m * m + EPSf);
        }
    }
}

// ---------------- BN apply + residual ------------------------------------
__global__ void bn_apply(const float* __restrict__ y, const float* __restrict__ x,
                         const float* __restrict__ mean, const float* __restrict__ istd,
                         const float* __restrict__ gamma, const float* __restrict__ beta,
                         float* __restrict__ out)
{
    const size_t i4 = ((size_t)blockIdx.x * blockDim.x + threadIdx.x) * 4;
    const size_t total = (size_t)Bn * Cn * Tn;
    if (i4 >= total) return;
    const int c = (int)((i4 / Tn) % Cn);
    const float g = gamma[c] * istd[c];
    const float m = mean[c];
    const float bt = beta[c];
    float4 yv = *(const float4*)(y + i4);
    float4 xv = *(const float4*)(x + i4);
    float4 o;
    o.x = g * (yv.x - m) + bt + xv.x;
    o.y = g * (yv.y - m) + bt + xv.y;
    o.z = g * (yv.z - m) + bt + xv.z;
    o.w = g * (yv.w - m) + bt + xv.w;
    *(float4*)(out + i4) = o;
}

extern "C" void kernel_launch(void* const* d_in, const int* in_sizes, int n_in,
                              void* d_out, int out_size)
{
    const float* x     = (const float*)d_in[0];
    const float* Wq    = (const float*)d_in[1];
    const float* bq    = (const float*)d_in[2];
    const float* Wk    = (const float*)d_in[3];
    const float* bk    = (const float*)d_in[4];
    const float* Wv    = (const float*)d_in[5];
    const float* bv    = (const float*)d_in[6];
    const float* Wo    = (const float*)d_in[7];
    const float* bo    = (const float*)d_in[8];
    const float* gamma = (const float*)d_in[9];
    const float* beta  = (const float*)d_in[10];
    float* out = (float*)d_out;

    float *q, *k, *v, *kp, *vp, *Mm, *o2, *yp, *mean, *istd;
    cudaGetSymbolAddress((void**)&q,    g_q);
    cudaGetSymbolAddress((void**)&k,    g_k);
    cudaGetSymbolAddress((void**)&v,    g_v);
    cudaGetSymbolAddress((void**)&kp,   g_kp);
    cudaGetSymbolAddress((void**)&vp,   g_vp);
    cudaGetSymbolAddress((void**)&Mm,   g_M);
    cudaGetSymbolAddress((void**)&o2,   g_o);
    cudaGetSymbolAddress((void**)&yp,   g_y);
    cudaGetSymbolAddress((void**)&mean, g_mean);
    cudaGetSymbolAddress((void**)&istd, g_istd);

    const dim3 blk(256);

    // Q,K,V projections: (D x T) = W (D x C) * x_b (C x T) + bias
    const dim3 g_proj(Tn / 128, Dn / 128, Bn);
    sgemm<false><<<g_proj, blk>>>(Wq, x, q, bq, Dn, Tn, Cn, 1.f,
                                  0, (size_t)Cn * Tn, (size_t)Dn * Tn);
    sgemm<false><<<g_proj, blk>>>(Wk, x, k, bk, Dn, Tn, Cn, 1.f,
                                  0, (size_t)Cn * Tn, (size_t)Dn * Tn);
    sgemm<false><<<g_proj, blk>>>(Wv, x, v, bv, Dn, Tn, Cn, 1.f,
                                  0, (size_t)Cn * Tn, (size_t)Dn * Tn);

    // MaxPool1d(2) on K and V along time
    const size_t npool = (size_t)Bn * Dn * Sn;
    pool2<<<(unsigned)((npool + 255) / 256), 256>>>(k, kp, npool);
    pool2<<<(unsigned)((npool + 255) / 256), 256>>>(v, vp, npool);

    // M_b = V_p K_p^T  (D x D, K = S)  [associativity: (VK^T)Q == V(K^T Q)]
    const dim3 g_m(Dn / 128, Dn / 128, Bn);
    sgemm<true><<<g_m, blk>>>(vp, kp, Mm, nullptr, Dn, Dn, Sn, 1.f,
                              (size_t)Dn * Sn, (size_t)Dn * Sn, (size_t)Dn * Dn);

    // out_b = (1/T) * M_b * Q_b   (D x T, K = D)
    const dim3 g_ogrid(Tn / 128, Dn / 128, Bn);
    sgemm<false><<<g_ogrid, blk>>>(Mm, q, o2, nullptr, Dn, Tn, Dn, 1.f / (float)Tn,
                                   (size_t)Dn * Dn, (size_t)Dn * Tn, (size_t)Dn * Tn);

    // y_b = Wo * out_b + bo   (C x T, K = D)
    const dim3 g_ygrid(Tn / 128, Cn / 128, Bn);
    sgemm<false><<<g_ygrid, blk>>>(Wo, o2, yp, bo, Cn, Tn, Dn, 1.f,
                                   0, (size_t)Dn * Tn, (size_t)Cn * Tn);

    // BatchNorm (training-mode batch stats) + residual
    bn_stats<<<Cn, 256>>>(yp, mean, istd);
    const size_t total4 = (size_t)Bn * Cn * Tn / 4;
    bn_apply<<<(unsigned)((total4 + 255) / 256), 256>>>(yp, x, mean, istd,
                                                        gamma, beta, out);
}

// round 3
// speedup vs baseline: 2.1468x; 2.1468x over previous
#include <cuda_runtime.h>
#include <cuda_bf16.h>

#define Bn 16
#define Cn 1024
#define Tn 2048
#define Dn 512
#define Sn (Tn / 2)
#define EPSf 1e-5f

typedef unsigned int u32;

// ---------------- scratch (static device arrays) ----------------
__device__ __align__(16) __nv_bfloat16 g_xth[(size_t)Bn * Tn * Cn];  // x^T hi (B,T,C)
__device__ __align__(16) __nv_bfloat16 g_xtl[(size_t)Bn * Tn * Cn];  // x^T lo
__device__ __align__(16) __nv_bfloat16 g_wqh[Dn * Cn], g_wql[Dn * Cn];
__device__ __align__(16) __nv_bfloat16 g_wkh[Dn * Cn], g_wkl[Dn * Cn];
__device__ __align__(16) __nv_bfloat16 g_wvh[Dn * Cn], g_wvl[Dn * Cn];
__device__ __align__(16) __nv_bfloat16 g_woh[Cn * Dn], g_wol[Cn * Dn];
__device__ __align__(16) __nv_bfloat16 g_qth[(size_t)Bn * Tn * Dn], g_qtl[(size_t)Bn * Tn * Dn]; // Q^T (B,T,D)
__device__ __align__(16) float         g_kf[(size_t)Bn * Dn * Tn];
__device__ __align__(16) float         g_vf[(size_t)Bn * Dn * Tn];
__device__ __align__(16) __nv_bfloat16 g_kph[(size_t)Bn * Dn * Sn], g_kpl[(size_t)Bn * Dn * Sn];
__device__ __align__(16) __nv_bfloat16 g_vph[(size_t)Bn * Dn * Sn], g_vpl[(size_t)Bn * Dn * Sn];
__device__ __align__(16) __nv_bfloat16 g_mh[(size_t)Bn * Dn * Dn], g_ml[(size_t)Bn * Dn * Dn];
__device__ __align__(16) __nv_bfloat16 g_oth[(size_t)Bn * Tn * Dn], g_otl[(size_t)Bn * Tn * Dn]; // out^T (B,T,D)
__device__ __align__(16) float         g_y[(size_t)Bn * Cn * Tn];
__device__ float g_mean[Cn];
__device__ float g_istd[Cn];

// ---------------- PTX helpers ----------------
__device__ __forceinline__ u32 smem_u32(const void* p) {
    u32 a;
    asm("{ .reg .u64 t; cvta.to.shared.u64 t, %1; cvt.u32.u64 %0, t; }" : "=r"(a) : "l"(p));
    return a;
}

#define CPA16(dst, src) \
    asm volatile("cp.async.cg.shared.global [%0], [%1], 16;" :: "r"(dst), "l"(src) : "memory")
#define CP_COMMIT() asm volatile("cp.async.commit_group;" ::: "memory")

#define LDSM4(r, a) \
    asm volatile("ldmatrix.sync.aligned.m8n8.x4.shared.b16 {%0,%1,%2,%3}, [%4];" \
        : "=r"((r)[0]), "=r"((r)[1]), "=r"((r)[2]), "=r"((r)[3]) : "r"(a))

#define MMA_BF16(d, a, b0, b1) \
    asm volatile("mma.sync.aligned.m16n8k16.row.col.f32.bf16.bf16.f32 " \
        "{%0,%1,%2,%3}, {%4,%5,%6,%7}, {%8,%9}, {%0,%1,%2,%3};" \
        : "+f"((d)[0]), "+f"((d)[1]), "+f"((d)[2]), "+f"((d)[3]) \
        : "r"((a)[0]), "r"((a)[1]), "r"((a)[2]), "r"((a)[3]), "r"(b0), "r"(b1))

__device__ __forceinline__ u32 pack_hi(float v0, float v1, float& r0, float& r1) {
    __nv_bfloat16 h0 = __float2bfloat16(v0);
    __nv_bfloat16 h1 = __float2bfloat16(v1);
    r0 = v0 - __bfloat162float(h0);
    r1 = v1 - __bfloat162float(h1);
    return (u32)__bfloat16_as_ushort(h0) | ((u32)__bfloat16_as_ushort(h1) << 16);
}
__device__ __forceinline__ u32 pack_lo(float r0, float r1) {
    __nv_bfloat16 l0 = __float2bfloat16(r0);
    __nv_bfloat16 l1 = __float2bfloat16(r1);
    return (u32)__bfloat16_as_ushort(l0) | ((u32)__bfloat16_as_ushort(l1) << 16);
}

// ---------------- warp-MMA split-bf16 GEMM ----------------
// C(M,N) = alpha * A(M,K) * Bt(N,K)^T + bias
// A, Bt both row-major K-major, given as bf16 hi/lo pairs.
// BIAS: 0 none, 1 per-row, 2 per-col. OUT_PAIR: write bf16 hi/lo, else fp32.
// CTA tile 128x128, BK=32, 8 warps each 32x64, cp.async double buffer.
// smem rows padded to 80B (40 bf16) -> conflict-free ldmatrix.
#define TILE_B 10240           // 128 rows * 80 B
#define BUF_B  (4 * TILE_B)    // Ah, Al, Bh, Bl
#define SMEM_B (2 * BUF_B)     // double buffered = 81920

template <int BIAS, bool OUT_PAIR>
__global__ void __launch_bounds__(256, 1) wgemm(
    const __nv_bfloat16* __restrict__ Ah, const __nv_bfloat16* __restrict__ Al,
    const __nv_bfloat16* __restrict__ Bth, const __nv_bfloat16* __restrict__ Btl,
    const float* __restrict__ bias,
    float* __restrict__ Cf, __nv_bfloat16* __restrict__ Ch, __nv_bfloat16* __restrict__ Cl,
    int M, int N, int K, float alpha,
    size_t sA, size_t sB, size_t sC)
{
    extern __shared__ __align__(128) char smem[];
    const u32 sbase = smem_u32(smem);
    const int tid = threadIdx.x;
    const int lane = tid & 31;
    const int warp = tid >> 5;
    const int wr = warp >> 1;       // 0..3 -> row block of 32
    const int wc = warp & 1;        // 0..1 -> col block of 64

    Ah  += (size_t)blockIdx.z * sA;  Al  += (size_t)blockIdx.z * sA;
    Bth += (size_t)blockIdx.z * sB;  Btl += (size_t)blockIdx.z * sB;
    const size_t coff = (size_t)blockIdx.z * sC;

    const int brow = blockIdx.y * 128;
    const int bcol = blockIdx.x * 128;
    const int KT = K >> 5;

    const __nv_bfloat16* srcs[4] = {Ah, Al, Bth, Btl};

    // loader: 4 tiles x 512 16B-chunks, 2 chunks per thread per tile
    auto load_tiles = [&](int buf, int kt) {
        const int k0 = kt << 5;
#pragma unroll
        for (int tile = 0; tile < 4; tile++) {
            const __nv_bfloat16* src = srcs[tile];
            const int rowbase = (tile < 2) ? brow : bcol;
            const u32 db = sbase + (u32)buf * BUF_B + (u32)tile * TILE_B;
#pragma unroll
            for (int it = 0; it < 2; it++) {
                const int idx = tid + it * 256;
                const int r = idx >> 2, ch = idx & 3;
                const __nv_bfloat16* g = src + (size_t)(rowbase + r) * K + k0 + ch * 8;
                CPA16(db + (u32)(r * 80 + ch * 16), g);
            }
        }
    };

    float acc[2][8][4];
#pragma unroll
    for (int i = 0; i < 2; i++)
#pragma unroll
        for (int j = 0; j < 8; j++)
#pragma unroll
            for (int q = 0; q < 4; q++) acc[i][j][q] = 0.f;

    load_tiles(0, 0);
    CP_COMMIT();

    const u32 rowoff = (u32)(((lane >> 3) & 1) * 8 + (lane & 7));
    const u32 chsel  = (u32)(lane >> 4);   // 0/1: which 16B chunk within k16

    for (int kt = 0; kt < KT; kt++) {
        const int buf = kt & 1;
        if (kt + 1 < KT) {
            load_tiles(buf ^ 1, kt + 1);
            CP_COMMIT();
            asm volatile("cp.async.wait_group 1;" ::: "memory");
        } else {
            asm volatile("cp.async.wait_group 0;" ::: "memory");
        }
        __syncthreads();

        const u32 at = sbase + (u32)buf * BUF_B;
#pragma unroll
        for (int ks = 0; ks < 2; ks++) {
            const u32 choff = (u32)(ks * 2 + chsel) * 16;
            u32 ah[2][4], al[2][4];
#pragma unroll
            for (int i = 0; i < 2; i++) {
                const u32 ad = at + (u32)(wr * 32 + i * 16 + rowoff) * 80 + choff;
                LDSM4(ah[i], ad);
                LDSM4(al[i], ad + TILE_B);
            }
            u32 bh[4][4], bl[4][4];
#pragma unroll
            for (int j4 = 0; j4 < 4; j4++) {
                const u32 bd = at + 2 * TILE_B + (u32)(wc * 64 + j4 * 16 + rowoff) * 80 + choff;
                LDSM4(bh[j4], bd);
                LDSM4(bl[j4], bd + TILE_B);
            }
#pragma unroll
            for (int i = 0; i < 2; i++)
#pragma unroll
                for (int j = 0; j < 8; j++) {
                    const int j4 = j >> 1, h = j & 1;
                    MMA_BF16(acc[i][j], ah[i], bh[j4][h], bh[j4][h + 2]);
                    MMA_BF16(acc[i][j], ah[i], bl[j4][h], bl[j4][h + 2]);
                    MMA_BF16(acc[i][j], al[i], bh[j4][h], bh[j4][h + 2]);
                }
        }
        __syncthreads();
    }

    // ---------------- epilogue ----------------
    const int r0 = brow + wr * 32 + (lane >> 2);
    const int c0 = bcol + wc * 64 + (lane & 3) * 2;
#pragma unroll
    for (int i = 0; i < 2; i++) {
#pragma unroll
        for (int half = 0; half < 2; half++) {
            const int row = r0 + i * 16 + half * 8;
            float badd_row = (BIAS == 1 && bias) ? bias[row] : 0.f;
#pragma unroll
            for (int j = 0; j < 8; j++) {
                const int col = c0 + j * 8;
                float v0 = alpha * acc[i][j][half * 2 + 0];
                float v1 = alpha * acc[i][j][half * 2 + 1];
                if (BIAS == 1) { v0 += badd_row; v1 += badd_row; }
                if (BIAS == 2) { v0 += bias[col]; v1 += bias[col + 1]; }
                const size_t o = coff + (size_t)row * N + col;
                if (OUT_PAIR) {
                    float rm0, rm1;
                    const u32 hp = pack_hi(v0, v1, rm0, rm1);
                    const u32 lp = pack_lo(rm0, rm1);
                    *(u32*)(Ch + o) = hp;
                    *(u32*)(Cl + o) = lp;
                } else {
                    *(float2*)(Cf + o) = make_float2(v0, v1);
                }
            }
        }
    }
}

// ---------------- x (B,C,T) fp32 -> x^T (B,T,C) bf16 hi/lo ----------------
__global__ void tsplit(const float* __restrict__ x,
                       __nv_bfloat16* __restrict__ oh, __nv_bfloat16* __restrict__ ol)
{
    __shared__ float s[32][33];
    const int b = blockIdx.z;
    const int c0 = blockIdx.y * 32;
    const int t0 = blockIdx.x * 32;
    const int tid = threadIdx.x;
    for (int i = tid; i < 1024; i += 256) {
        const int r = i >> 5, cc = i & 31;
        s[r][cc] = x[((size_t)b * Cn + c0 + r) * Tn + t0 + cc];
    }
    __syncthreads();
    for (int i = tid; i < 512; i += 256) {
        const int r = i >> 4, cp = (i & 15) * 2;
        const float v0 = s[cp][r], v1 = s[cp + 1][r];
        float rm0, rm1;
        const u32 hp = pack_hi(v0, v1, rm0, rm1);
        const u32 lp = pack_lo(rm0, rm1);
        const size_t o = ((size_t)b * Tn + t0 + r) * Cn + c0 + cp;
        *(u32*)(oh + o) = hp;
        *(u32*)(ol + o) = lp;
    }
}

// ---------------- fp32 -> bf16 hi/lo split (weights) ----------------
__global__ void split_kernel(const float* __restrict__ in,
                             __nv_bfloat16* __restrict__ oh, __nv_bfloat16* __restrict__ ol,
                             size_t n4)
{
    const size_t i = (size_t)blockIdx.x * blockDim.x + threadIdx.x;
    if (i >= n4) return;
    const float4 v = ((const float4*)in)[i];
    float rm0, rm1, rm2, rm3;
    const u32 h0 = pack_hi(v.x, v.y, rm0, rm1);
    const u32 h1 = pack_hi(v.z, v.w, rm2, rm3);
    const u32 l0 = pack_lo(rm0, rm1);
    const u32 l1 = pack_lo(rm2, rm3);
    ((uint2*)oh)[i] = make_uint2(h0, h1);
    ((uint2*)ol)[i] = make_uint2(l0, l1);
}

// ---------------- MaxPool1d(2) + bf16 hi/lo split ----------------
__global__ void pool_split(const float* __restrict__ in,
                           __nv_bfloat16* __restrict__ oh, __nv_bfloat16* __restrict__ ol,
                           size_t n4)
{
    const size_t i = (size_t)blockIdx.x * blockDim.x + threadIdx.x;
    if (i >= n4) return;
    const float4 a = ((const float4*)in)[2 * i];
    const float4 b = ((const float4*)in)[2 * i + 1];
    float rm0, rm1, rm2, rm3;
    const u32 h0 = pack_hi(fmaxf(a.x, a.y), fmaxf(a.z, a.w), rm0, rm1);
    const u32 h1 = pack_hi(fmaxf(b.x, b.y), fmaxf(b.z, b.w), rm2, rm3);
    const u32 l0 = pack_lo(rm0, rm1);
    const u32 l1 = pack_lo(rm2, rm3);
    ((uint2*)oh)[i] = make_uint2(h0, h1);
    ((uint2*)ol)[i] = make_uint2(l0, l1);
}

// ---------------- BN batch stats ----------------
__global__ void bn_stats(const float* __restrict__ y,
                         float* __restrict__ mean, float* __restrict__ istd)
{
    const int c = blockIdx.x;
    float s = 0.f, s2 = 0.f;
    for (int b = 0; b < Bn; b++) {
        const float* row = y + ((size_t)b * Cn + c) * Tn;
        for (int t = threadIdx.x * 4; t < Tn; t += blockDim.x * 4) {
            float4 v = *(const float4*)(row + t);
            s  += v.x + v.y + v.z + v.w;
            s2 += v.x * v.x + v.y * v.y + v.z * v.z + v.w * v.w;
        }
    }
#pragma unroll
    for (int o = 16; o > 0; o >>= 1) {
        s  += __shfl_down_sync(0xffffffffu, s,  o);
        s2 += __shfl_down_sync(0xffffffffu, s2, o);
    }
    __shared__ float ss[32], ss2[32];
    const int lane = threadIdx.x & 31, w = threadIdx.x >> 5;
    if (lane == 0) { ss[w] = s; ss2[w] = s2; }
    __syncthreads();
    if (w == 0) {
        const int nw = blockDim.x >> 5;
        s  = lane < nw ? ss[lane]  : 0.f;
        s2 = lane < nw ? ss2[lane] : 0.f;
#pragma unroll
        for (int o = 16; o > 0; o >>= 1) {
            s  += __shfl_down_sync(0xffffffffu, s,  o);
            s2 += __shfl_down_sync(0xffffffffu, s2, o);
        }
        if (lane == 0) {
            const float n = (float)(Bn * Tn);
            const float m = s / n;
            mean[c] = m;
            istd[c] = rsqrtf(s2 / n - m * m + EPSf);
        }
    }
}

// ---------------- BN apply + residual ----------------
__global__ void bn_apply(const float* __restrict__ y, const float* __restrict__ x,
                         const float* __restrict__ mean, const float* __restrict__ istd,
                         const float* __restrict__ gamma, const float* __restrict__ beta,
                         float* __restrict__ out)
{
    const size_t i4 = ((size_t)blockIdx.x * blockDim.x + threadIdx.x) * 4;
    const size_t total = (size_t)Bn * Cn * Tn;
    if (i4 >= total) return;
    const int c = (int)((i4 / Tn) % Cn);
    const float g = gamma[c] * istd[c];
    const float m = mean[c];
    const float bt = beta[c];
    float4 yv = *(const float4*)(y + i4);
    float4 xv = *(const float4*)(x + i4);
    float4 o;
    o.x = g * (yv.x - m) + bt + xv.x;
    o.y = g * (yv.y - m) + bt + xv.y;
    o.z = g * (yv.z - m) + bt + xv.z;
    o.w = g * (yv.w - m) + bt + xv.w;
    *(float4*)(out + i4) = o;
}

extern "C" void kernel_launch(void* const* d_in, const int* in_sizes, int n_in,
                              void* d_out, int out_size)
{
    const float* x     = (const float*)d_in[0];
    const float* Wq    = (const float*)d_in[1];
    const float* bq    = (const float*)d_in[2];
    const float* Wk    = (const float*)d_in[3];
    const float* bk    = (const float*)d_in[4];
    const float* Wv    = (const float*)d_in[5];
    const float* bv    = (const float*)d_in[6];
    const float* Wo    = (const float*)d_in[7];
    const float* bo    = (const float*)d_in[8];
    const float* gamma = (const float*)d_in[9];
    const float* beta  = (const float*)d_in[10];
    float* out = (float*)d_out;

    __nv_bfloat16 *xth, *xtl, *wqh, *wql, *wkh, *wkl, *wvh, *wvl, *woh, *wol;
    __nv_bfloat16 *qth, *qtl, *kph, *kpl, *vph, *vpl, *mh, *ml, *oth, *otl;
    float *kf, *vf, *yp, *mean, *istd;
    cudaGetSymbolAddress((void**)&xth, g_xth);  cudaGetSymbolAddress((void**)&xtl, g_xtl);
    cudaGetSymbolAddress((void**)&wqh, g_wqh);  cudaGetSymbolAddress((void**)&wql, g_wql);
    cudaGetSymbolAddress((void**)&wkh, g_wkh);  cudaGetSymbolAddress((void**)&wkl, g_wkl);
    cudaGetSymbolAddress((void**)&wvh, g_wvh);  cudaGetSymbolAddress((void**)&wvl, g_wvl);
    cudaGetSymbolAddress((void**)&woh, g_woh);  cudaGetSymbolAddress((void**)&wol, g_wol);
    cudaGetSymbolAddress((void**)&qth, g_qth);  cudaGetSymbolAddress((void**)&qtl, g_qtl);
    cudaGetSymbolAddress((void**)&kf,  g_kf);   cudaGetSymbolAddress((void**)&vf,  g_vf);
    cudaGetSymbolAddress((void**)&kph, g_kph);  cudaGetSymbolAddress((void**)&kpl, g_kpl);
    cudaGetSymbolAddress((void**)&vph, g_vph);  cudaGetSymbolAddress((void**)&vpl, g_vpl);
    cudaGetSymbolAddress((void**)&mh,  g_mh);   cudaGetSymbolAddress((void**)&ml,  g_ml);
    cudaGetSymbolAddress((void**)&oth, g_oth);  cudaGetSymbolAddress((void**)&otl, g_otl);
    cudaGetSymbolAddress((void**)&yp,  g_y);
    cudaGetSymbolAddress((void**)&mean, g_mean);
    cudaGetSymbolAddress((void**)&istd, g_istd);

    cudaFuncSetAttribute(wgemm<1, false>, cudaFuncAttributeMaxDynamicSharedMemorySize, SMEM_B);
    cudaFuncSetAttribute(wgemm<2, true>,  cudaFuncAttributeMaxDynamicSharedMemorySize, SMEM_B);
    cudaFuncSetAttribute(wgemm<0, true>,  cudaFuncAttributeMaxDynamicSharedMemorySize, SMEM_B);

    // x transpose + split, weight splits
    tsplit<<<dim3(Tn / 32, Cn / 32, Bn), 256>>>(x, xth, xtl);
    const size_t nw4 = (size_t)Dn * Cn / 4;
    split_kernel<<<(unsigned)((nw4 + 255) / 256), 256>>>(Wq, wqh, wql, nw4);
    split_kernel<<<(unsigned)((nw4 + 255) / 256), 256>>>(Wk, wkh, wkl, nw4);
    split_kernel<<<(unsigned)((nw4 + 255) / 256), 256>>>(Wv, wvh, wvl, nw4);
    split_kernel<<<(unsigned)((nw4 + 255) / 256), 256>>>(Wo, woh, wol, nw4);

    const size_t sTC = (size_t)Tn * Cn;
    const size_t sDT = (size_t)Dn * Tn;
    const size_t sTD = (size_t)Tn * Dn;
    const size_t sDS = (size_t)Dn * Sn;
    const size_t sDD = (size_t)Dn * Dn;
    const size_t sCT = (size_t)Cn * Tn;

    // K,V proj: C(D,T) = W(D,C) x; A=W, Bt=xT(T,C)  -> fp32, row bias
    const dim3 gkv(Tn / 128, Dn / 128, Bn);
    wgemm<1, false><<<gkv, 256, SMEM_B>>>(wkh, wkl, xth, xtl, bk, kf, nullptr, nullptr,
                                          Dn, Tn, Cn, 1.f, 0, sTC, sDT);
    wgemm<1, false><<<gkv, 256, SMEM_B>>>(wvh, wvl, xth, xtl, bv, vf, nullptr, nullptr,
                                          Dn, Tn, Cn, 1.f, 0, sTC, sDT);

    // Q^T: C(T,D) = xT(T,C) Wq^T; A=xT, Bt=Wq(D,C) -> pair, col bias
    const dim3 gq(Dn / 128, Tn / 128, Bn);
    wgemm<2, true><<<gq, 256, SMEM_B>>>(xth, xtl, wqh, wql, bq, nullptr, qth, qtl,
                                        Tn, Dn, Cn, 1.f, sTC, 0, sTD);

    // pools
    const size_t np4 = (size_t)Bn * Dn * Sn / 4;
    pool_split<<<(unsigned)((np4 + 255) / 256), 256>>>(kf, kph, kpl, np4);
    pool_split<<<(unsigned)((np4 + 255) / 256), 256>>>(vf, vph, vpl, np4);

    // M(D,D) = Vp Kp^T; A=Vp(D,S), Bt=Kp(D,S) -> pair
    const dim3 gm(Dn / 128, Dn / 128, Bn);
    wgemm<0, true><<<gm, 256, SMEM_B>>>(vph, vpl, kph, kpl, nullptr, nullptr, mh, ml,
                                        Dn, Dn, Sn, 1.f, sDS, sDS, sDD);

    // out^T(T,D) = (1/T) Q^T M^T; A=QT(T,D), Bt=M(D,D) -> pair
    const dim3 go(Dn / 128, Tn / 128, Bn);
    wgemm<0, true><<<go, 256, SMEM_B>>>(qth, qtl, mh, ml, nullptr, nullptr, oth, otl,
                                        Tn, Dn, Dn, 1.f / (float)Tn, sTD, sDD, sTD);

    // y(C,T) = Wo out + bo; A=Wo(C,D), Bt=outT(T,D) -> fp32, row bias
    const dim3 gy(Tn / 128, Cn / 128, Bn);
    wgemm<1, false><<<gy, 256, SMEM_B>>>(woh, wol, oth, otl, bo, yp, nullptr, nullptr,
                                         Cn, Tn, Dn, 1.f, 0, sTD, sCT);

    // BatchNorm + residual
    bn_stats<<<Cn, 256>>>(yp, mean, istd);
    const size_t total4 = (size_t)Bn * Cn * Tn / 4;
    bn_apply<<<(unsigned)((total4 + 255) / 256), 256>>>(yp, x, mean, istd, gamma, beta, out);
}

// round 4
// speedup vs baseline: 3.2059x; 1.4933x over previous
#include <cuda_runtime.h>
#include <cuda_fp16.h>

#define Bn 16
#define Cn 1024
#define Tn 2048
#define Dn 512
#define Sn (Tn / 2)
#define EPSf 1e-5f

typedef unsigned int u32;

// ---------------- scratch (static device arrays) ----------------
__device__ __align__(16) __half g_xt [(size_t)Bn * Tn * Cn];              // x^T (B,T,C) single
__device__ __align__(16) __half g_wqh[Dn * Cn], g_wql[Dn * Cn];
__device__ __align__(16) __half g_wkh[Dn * Cn], g_wkl[Dn * Cn];
__device__ __align__(16) __half g_wvh[Dn * Cn], g_wvl[Dn * Cn];
__device__ __align__(16) __half g_woh[Cn * Dn], g_wol[Cn * Dn];
__device__ __align__(16) __half g_q  [(size_t)Bn * Dn * Tn];              // Q (B,D,T) single
__device__ __align__(16) __half g_qt [(size_t)Bn * Tn * Dn];              // Q^T (B,T,D)
__device__ __align__(16) __half g_kp [(size_t)Bn * Dn * Sn];              // pooled K single
__device__ __align__(16) __half g_vph[(size_t)Bn * Dn * Sn], g_vpl[(size_t)Bn * Dn * Sn]; // pooled V pair
__device__ __align__(16) __half g_mh [(size_t)Bn * Dn * Dn], g_ml [(size_t)Bn * Dn * Dn]; // M pair
__device__ __align__(16) __half g_o  [(size_t)Bn * Dn * Tn];              // out (B,D,T) single
__device__ __align__(16) __half g_ot [(size_t)Bn * Tn * Dn];              // out^T (B,T,D)
__device__ __align__(16) float  g_y  [(size_t)Bn * Cn * Tn];
__device__ float g_mean[Cn];
__device__ float g_istd[Cn];

// ---------------- PTX helpers ----------------
__device__ __forceinline__ u32 smem_u32(const void* p) {
    u32 a;
    asm("{ .reg .u64 t; cvta.to.shared.u64 t, %1; cvt.u32.u64 %0, t; }" : "=r"(a) : "l"(p));
    return a;
}

#define CPA16(dst, src) \
    asm volatile("cp.async.cg.shared.global [%0], [%1], 16;" :: "r"(dst), "l"(src) : "memory")
#define CP_COMMIT() asm volatile("cp.async.commit_group;" ::: "memory")

#define LDSM4(r, a) \
    asm volatile("ldmatrix.sync.aligned.m8n8.x4.shared.b16 {%0,%1,%2,%3}, [%4];" \
        : "=r"((r)[0]), "=r"((r)[1]), "=r"((r)[2]), "=r"((r)[3]) : "r"(a))

#define MMA_F16(d, a, b0, b1) \
    asm volatile("mma.sync.aligned.m16n8k16.row.col.f32.f16.f16.f32 " \
        "{%0,%1,%2,%3}, {%4,%5,%6,%7}, {%8,%9}, {%0,%1,%2,%3};" \
        : "+f"((d)[0]), "+f"((d)[1]), "+f"((d)[2]), "+f"((d)[3]) \
        : "r"((a)[0]), "r"((a)[1]), "r"((a)[2]), "r"((a)[3]), "r"(b0), "r"(b1))

__device__ __forceinline__ u32 pack_h2(float v0, float v1) {
    __half h0 = __float2half_rn(v0), h1 = __float2half_rn(v1);
    return (u32)__half_as_ushort(h0) | ((u32)__half_as_ushort(h1) << 16);
}

// ---------------- warp-MMA fp16 2-term split GEMM ----------------
// C(M,N) = alpha * (Ah+Al)(M,K) * Bt(N,K)^T + bias
// A split into fp16 hi/lo; Bt single fp16. Both row-major K-major.
// BIAS: 0 none, 1 per-row.
// OMODE: 0 fp32 out; 1 fp16 single; 2 fp16 pair; 3 pool2->fp16 single; 4 pool2->fp16 pair.
// CTA 128x128, BK=32, 8 warps (32x64 each), cp.async double buffer,
// 80B-padded smem rows (conflict-free ldmatrix).
#define TILE_B 10240           // 128 rows * 80 B
#define BUF_B  (3 * TILE_B)    // Ah, Al, B
#define SMEM_B (2 * BUF_B)     // double buffered = 61440

template <int BIAS, int OMODE>
__global__ void __launch_bounds__(256) wgemm(
    const __half* __restrict__ Ah, const __half* __restrict__ Al,
    const __half* __restrict__ Bt,
    const float* __restrict__ bias,
    float* __restrict__ Cf, __half* __restrict__ Ch, __half* __restrict__ Cl,
    int M, int N, int K, float alpha,
    size_t sA, size_t sB, size_t sC)
{
    extern __shared__ __align__(128) char smem[];
    const u32 sbase = smem_u32(smem);
    const int tid = threadIdx.x;
    const int lane = tid & 31;
    const int warp = tid >> 5;
    const int wr = warp >> 1;       // 0..3 -> 32-row block
    const int wc = warp & 1;        // 0..1 -> 64-col block

    Ah += (size_t)blockIdx.z * sA;  Al += (size_t)blockIdx.z * sA;
    Bt += (size_t)blockIdx.z * sB;
    const size_t coff = (size_t)blockIdx.z * sC;

    const int brow = blockIdx.y * 128;
    const int bcol = blockIdx.x * 128;
    const int KT = K >> 5;

    const __half* srcs[3] = {Ah, Al, Bt};

    auto load_tiles = [&](int buf, int kt) {
        const int k0 = kt << 5;
#pragma unroll
        for (int tile = 0; tile < 3; tile++) {
            const __half* src = srcs[tile];
            const int rowbase = (tile < 2) ? brow : bcol;
            const u32 db = sbase + (u32)buf * BUF_B + (u32)tile * TILE_B;
#pragma unroll
            for (int it = 0; it < 2; it++) {
                const int idx = tid + it * 256;
                const int r = idx >> 2, ch = idx & 3;
                const __half* g = src + (size_t)(rowbase + r) * K + k0 + ch * 8;
                CPA16(db + (u32)(r * 80 + ch * 16), g);
            }
        }
    };

    float acc[2][8][4];
#pragma unroll
    for (int i = 0; i < 2; i++)
#pragma unroll
        for (int j = 0; j < 8; j++)
#pragma unroll
            for (int q = 0; q < 4; q++) acc[i][j][q] = 0.f;

    load_tiles(0, 0);
    CP_COMMIT();

    const u32 rowoff = (u32)(((lane >> 3) & 1) * 8 + (lane & 7));
    const u32 chsel  = (u32)(lane >> 4);

    for (int kt = 0; kt < KT; kt++) {
        const int buf = kt & 1;
        if (kt + 1 < KT) {
            load_tiles(buf ^ 1, kt + 1);
            CP_COMMIT();
            asm volatile("cp.async.wait_group 1;" ::: "memory");
        } else {
            asm volatile("cp.async.wait_group 0;" ::: "memory");
        }
        __syncthreads();

        const u32 at = sbase + (u32)buf * BUF_B;
#pragma unroll
        for (int ks = 0; ks < 2; ks++) {
            const u32 choff = (u32)(ks * 2 + chsel) * 16;
            u32 ah[2][4], al[2][4];
#pragma unroll
            for (int i = 0; i < 2; i++) {
                const u32 ad = at + (u32)(wr * 32 + i * 16 + rowoff) * 80 + choff;
                LDSM4(ah[i], ad);
                LDSM4(al[i], ad + TILE_B);
            }
            u32 bh[4][4];
#pragma unroll
            for (int j4 = 0; j4 < 4; j4++) {
                const u32 bd = at + 2 * TILE_B + (u32)(wc * 64 + j4 * 16 + rowoff) * 80 + choff;
                LDSM4(bh[j4], bd);
            }
#pragma unroll
            for (int i = 0; i < 2; i++)
#pragma unroll
                for (int j = 0; j < 8; j++) {
                    const int j4 = j >> 1, h = j & 1;
                    MMA_F16(acc[i][j], ah[i], bh[j4][h], bh[j4][h + 2]);
                    MMA_F16(acc[i][j], al[i], bh[j4][h], bh[j4][h + 2]);
                }
        }
        __syncthreads();
    }

    // ---------------- epilogue ----------------
    const int r0 = brow + wr * 32 + (lane >> 2);
    const int c0l = wc * 64 + (lane & 3) * 2;
#pragma unroll
    for (int i = 0; i < 2; i++) {
#pragma unroll
        for (int half = 0; half < 2; half++) {
            const int row = r0 + i * 16 + half * 8;
            const float badd = (BIAS == 1) ? bias[row] : 0.f;
#pragma unroll
            for (int j = 0; j < 8; j++) {
                const int col = bcol + c0l + j * 8;
                const float v0 = alpha * acc[i][j][half * 2 + 0] + badd;
                const float v1 = alpha * acc[i][j][half * 2 + 1] + badd;
                if (OMODE == 0) {
                    *(float2*)(Cf + coff + (size_t)row * N + col) = make_float2(v0, v1);
                } else if (OMODE == 1) {
                    *(u32*)(Ch + coff + (size_t)row * N + col) = pack_h2(v0, v1);
                } else if (OMODE == 2) {
                    __half h0 = __float2half_rn(v0), h1 = __float2half_rn(v1);
                    __half l0 = __float2half_rn(v0 - __half2float(h0));
                    __half l1 = __float2half_rn(v1 - __half2float(h1));
                    const size_t o = coff + (size_t)row * N + col;
                    *(u32*)(Ch + o) = (u32)__half_as_ushort(h0) | ((u32)__half_as_ushort(h1) << 16);
                    *(u32*)(Cl + o) = (u32)__half_as_ushort(l0) | ((u32)__half_as_ushort(l1) << 16);
                } else if (OMODE == 3) {
                    const float m = fmaxf(v0, v1);
                    Ch[coff + (size_t)row * (N >> 1) + (col >> 1)] = __float2half_rn(m);
                } else { // OMODE == 4
                    const float m = fmaxf(v0, v1);
                    const __half h = __float2half_rn(m);
                    const __half l = __float2half_rn(m - __half2float(h));
                    const size_t o = coff + (size_t)row * (N >> 1) + (col >> 1);
                    Ch[o] = h;
                    Cl[o] = l;
                }
            }
        }
    }
}

// ---------------- x (B,C,T) fp32 -> x^T (B,T,C) fp16 ----------------
__global__ void xtrans(const float* __restrict__ x, __half* __restrict__ o)
{
    __shared__ float s[32][33];
    const int b = blockIdx.z;
    const int c0 = blockIdx.y * 32;
    const int t0 = blockIdx.x * 32;
    const int tid = threadIdx.x;
    for (int i = tid; i < 1024; i += 256) {
        const int r = i >> 5, cc = i & 31;
        s[r][cc] = x[((size_t)b * Cn + c0 + r) * Tn + t0 + cc];
    }
    __syncthreads();
    for (int i = tid; i < 512; i += 256) {
        const int r = i >> 4, cp = (i & 15) * 2;
        const size_t oo = ((size_t)b * Tn + t0 + r) * Cn + c0 + cp;
        *(u32*)(o + oo) = pack_h2(s[cp][r], s[cp + 1][r]);
    }
}

// ---------------- batched fp16 transpose: (R,Cc) -> (Cc,R) ----------------
__global__ void htrans(const __half* __restrict__ in, __half* __restrict__ out,
                       int R, int Cc)
{
    __shared__ __half s[32][33];
    const int b = blockIdx.z;
    const int r0 = blockIdx.y * 32;
    const int c0 = blockIdx.x * 32;
    const int tid = threadIdx.x;
    const size_t off = (size_t)b * R * Cc;
    for (int i = tid; i < 1024; i += 256) {
        const int r = i >> 5, c = i & 31;
        s[r][c] = in[off + (size_t)(r0 + r) * Cc + c0 + c];
    }
    __syncthreads();
    for (int i = tid; i < 512; i += 256) {
        const int r = i >> 4, cp = (i & 15) * 2;
        const size_t oo = off + (size_t)(c0 + r) * R + r0 + cp;
        __half a = s[cp][r], c2 = s[cp + 1][r];
        *(u32*)(out + oo) = (u32)__half_as_ushort(a) | ((u32)__half_as_ushort(c2) << 16);
    }
}

// ---------------- fp32 -> fp16 hi/lo split (weights) ----------------
__global__ void wsplit(const float* __restrict__ in,
                       __half* __restrict__ oh, __half* __restrict__ ol, size_t n4)
{
    const size_t i = (size_t)blockIdx.x * blockDim.x + threadIdx.x;
    if (i >= n4) return;
    const float4 v = ((const float4*)in)[i];
    const float f[4] = {v.x, v.y, v.z, v.w};
    u32 hp[2], lp[2];
#pragma unroll
    for (int q = 0; q < 2; q++) {
        __half h0 = __float2half_rn(f[q * 2 + 0]);
        __half h1 = __float2half_rn(f[q * 2 + 1]);
        __half l0 = __float2half_rn(f[q * 2 + 0] - __half2float(h0));
        __half l1 = __float2half_rn(f[q * 2 + 1] - __half2float(h1));
        hp[q] = (u32)__half_as_ushort(h0) | ((u32)__half_as_ushort(h1) << 16);
        lp[q] = (u32)__half_as_ushort(l0) | ((u32)__half_as_ushort(l1) << 16);
    }
    ((uint2*)oh)[i] = make_uint2(hp[0], hp[1]);
    ((uint2*)ol)[i] = make_uint2(lp[0], lp[1]);
}

// ---------------- BN batch stats ----------------
__global__ void bn_stats(const float* __restrict__ y,
                         float* __restrict__ mean, float* __restrict__ istd)
{
    const int c = blockIdx.x;
    float s = 0.f, s2 = 0.f;
    for (int b = 0; b < Bn; b++) {
        const float* row = y + ((size_t)b * Cn + c) * Tn;
        for (int t = threadIdx.x * 4; t < Tn; t += blockDim.x * 4) {
            float4 v = *(const float4*)(row + t);
            s  += v.x + v.y + v.z + v.w;
            s2 += v.x * v.x + v.y * v.y + v.z * v.z + v.w * v.w;
        }
    }
#pragma unroll
    for (int o = 16; o > 0; o >>= 1) {
        s  += __shfl_down_sync(0xffffffffu, s,  o);
        s2 += __shfl_down_sync(0xffffffffu, s2, o);
    }
    __shared__ float ss[32], ss2[32];
    const int lane = threadIdx.x & 31, w = threadIdx.x >> 5;
    if (lane == 0) { ss[w] = s; ss2[w] = s2; }
    __syncthreads();
    if (w == 0) {
        const int nw = blockDim.x >> 5;
        s  = lane < nw ? ss[lane]  : 0.f;
        s2 = lane < nw ? ss2[lane] : 0.f;
#pragma unroll
        for (int o = 16; o > 0; o >>= 1) {
            s  += __shfl_down_sync(0xffffffffu, s,  o);
            s2 += __shfl_down_sync(0xffffffffu, s2, o);
        }
        if (lane == 0) {
            const float n = (float)(Bn * Tn);
            const float m = s / n;
            mean[c] = m;
            istd[c] = rsqrtf(s2 / n - m * m + EPSf);
        }
    }
}

// ---------------- BN apply + residual ----------------
__global__ void bn_apply(const float* __restrict__ y, const float* __restrict__ x,
                         const float* __restrict__ mean, const float* __restrict__ istd,
                         const float* __restrict__ gamma, const float* __restrict__ beta,
                         float* __restrict__ out)
{
    const size_t i4 = ((size_t)blockIdx.x * blockDim.x + threadIdx.x) * 4;
    const size_t total = (size_t)Bn * Cn * Tn;
    if (i4 >= total) return;
    const int c = (int)((i4 / Tn) % Cn);
    const float g = gamma[c] * istd[c];
    const float m = mean[c];
    const float bt = beta[c];
    float4 yv = *(const float4*)(y + i4);
    float4 xv = *(const float4*)(x + i4);
    float4 o;
    o.x = g * (yv.x - m) + bt + xv.x;
    o.y = g * (yv.y - m) + bt + xv.y;
    o.z = g * (yv.z - m) + bt + xv.z;
    o.w = g * (yv.w - m) + bt + xv.w;
    *(float4*)(out + i4) = o;
}

extern "C" void kernel_launch(void* const* d_in, const int* in_sizes, int n_in,
                              void* d_out, int out_size)
{
    const float* x     = (const float*)d_in[0];
    const float* Wq    = (const float*)d_in[1];
    const float* bq    = (const float*)d_in[2];
    const float* Wk    = (const float*)d_in[3];
    const float* bk    = (const float*)d_in[4];
    const float* Wv    = (const float*)d_in[5];
    const float* bv    = (const float*)d_in[6];
    const float* Wo    = (const float*)d_in[7];
    const float* bo    = (const float*)d_in[8];
    const float* gamma = (const float*)d_in[9];
    const float* beta  = (const float*)d_in[10];
    float* out = (float*)d_out;

    __half *xt, *wqh, *wql, *wkh, *wkl, *wvh, *wvl, *woh, *wol;
    __half *q, *qt, *kp, *vph, *vpl, *mh, *ml, *o, *ot;
    float *yp, *mean, *istd;
    cudaGetSymbolAddress((void**)&xt,  g_xt);
    cudaGetSymbolAddress((void**)&wqh, g_wqh);  cudaGetSymbolAddress((void**)&wql, g_wql);
    cudaGetSymbolAddress((void**)&wkh, g_wkh);  cudaGetSymbolAddress((void**)&wkl, g_wkl);
    cudaGetSymbolAddress((void**)&wvh, g_wvh);  cudaGetSymbolAddress((void**)&wvl, g_wvl);
    cudaGetSymbolAddress((void**)&woh, g_woh);  cudaGetSymbolAddress((void**)&wol, g_wol);
    cudaGetSymbolAddress((void**)&q,   g_q);    cudaGetSymbolAddress((void**)&qt,  g_qt);
    cudaGetSymbolAddress((void**)&kp,  g_kp);
    cudaGetSymbolAddress((void**)&vph, g_vph);  cudaGetSymbolAddress((void**)&vpl, g_vpl);
    cudaGetSymbolAddress((void**)&mh,  g_mh);   cudaGetSymbolAddress((void**)&ml,  g_ml);
    cudaGetSymbolAddress((void**)&o,   g_o);    cudaGetSymbolAddress((void**)&ot,  g_ot);
    cudaGetSymbolAddress((void**)&yp,  g_y);
    cudaGetSymbolAddress((void**)&mean, g_mean);
    cudaGetSymbolAddress((void**)&istd, g_istd);

    cudaFuncSetAttribute(wgemm<1, 3>, cudaFuncAttributeMaxDynamicSharedMemorySize, SMEM_B);
    cudaFuncSetAttribute(wgemm<1, 4>, cudaFuncAttributeMaxDynamicSharedMemorySize, SMEM_B);
    cudaFuncSetAttribute(wgemm<1, 1>, cudaFuncAttributeMaxDynamicSharedMemorySize, SMEM_B);
    cudaFuncSetAttribute(wgemm<0, 2>, cudaFuncAttributeMaxDynamicSharedMemorySize, SMEM_B);
    cudaFuncSetAttribute(wgemm<0, 1>, cudaFuncAttributeMaxDynamicSharedMemorySize, SMEM_B);
    cudaFuncSetAttribute(wgemm<1, 0>, cudaFuncAttributeMaxDynamicSharedMemorySize, SMEM_B);

    // conversions
    xtrans<<<dim3(Tn / 32, Cn / 32, Bn), 256>>>(x, xt);
    const size_t nw4 = (size_t)Dn * Cn / 4;
    wsplit<<<(unsigned)((nw4 + 255) / 256), 256>>>(Wq, wqh, wql, nw4);
    wsplit<<<(unsigned)((nw4 + 255) / 256), 256>>>(Wk, wkh, wkl, nw4);
    wsplit<<<(unsigned)((nw4 + 255) / 256), 256>>>(Wv, wvh, wvl, nw4);
    wsplit<<<(unsigned)((nw4 + 255) / 256), 256>>>(Wo, woh, wol, nw4);

    const size_t sTC = (size_t)Tn * Cn;
    const size_t sDT = (size_t)Dn * Tn;
    const size_t sTD = (size_t)Tn * Dn;
    const size_t sDS = (size_t)Dn * Sn;
    const size_t sDD = (size_t)Dn * Dn;
    const size_t sCT = (size_t)Cn * Tn;

    // K proj + fused pool: Kp(D,S) <- pool2(Wk x + bk); A=Wk split, Bt=xT
    const dim3 gkv(Tn / 128, Dn / 128, Bn);
    wgemm<1, 3><<<gkv, 256, SMEM_B>>>(wkh, wkl, xt, bk, nullptr, kp, nullptr,
                                      Dn, Tn, Cn, 1.f, 0, sTC, sDS);
    // V proj + fused pool -> pair
    wgemm<1, 4><<<gkv, 256, SMEM_B>>>(wvh, wvl, xt, bv, nullptr, vph, vpl,
                                      Dn, Tn, Cn, 1.f, 0, sTC, sDS);
    // Q proj: Q(D,T) single
    wgemm<1, 1><<<gkv, 256, SMEM_B>>>(wqh, wql, xt, bq, nullptr, q, nullptr,
                                      Dn, Tn, Cn, 1.f, 0, sTC, sDT);
    // Q^T (T,D)
    htrans<<<dim3(Tn / 32, Dn / 32, Bn), 256>>>(q, qt, Dn, Tn);

    // M(D,D) = Vp Kp^T : A=Vp pair, Bt=Kp single -> pair
    const dim3 gm(Dn / 128, Dn / 128, Bn);
    wgemm<0, 2><<<gm, 256, SMEM_B>>>(vph, vpl, kp, nullptr, nullptr, mh, ml,
                                     Dn, Dn, Sn, 1.f, sDS, sDS, sDD);

    // out(D,T) = (1/T) M Q : A=M pair, Bt=Q^T single -> single
    const dim3 go(Tn / 128, Dn / 128, Bn);
    wgemm<0, 1><<<go, 256, SMEM_B>>>(mh, ml, qt, nullptr, nullptr, o, nullptr,
                                     Dn, Tn, Dn, 1.f / (float)Tn, sDD, sTD, sDT);
    // out^T (T,D)
    htrans<<<dim3(Tn / 32, Dn / 32, Bn), 256>>>(o, ot, Dn, Tn);

    // y(C,T) = Wo out + bo : A=Wo split, Bt=out^T single -> fp32
    const dim3 gy(Tn / 128, Cn / 128, Bn);
    wgemm<1, 0><<<gy, 256, SMEM_B>>>(woh, wol, ot, bo, yp, nullptr, nullptr,
                                     Cn, Tn, Dn, 1.f, 0, sTD, sCT);

    // BatchNorm + residual
    bn_stats<<<Cn, 256>>>(yp, mean, istd);
    const size_t total4 = (size_t)Bn * Cn * Tn / 4;
    bn_apply<<<(unsigned)((total4 + 255) / 256), 256>>>(yp, x, mean, istd, gamma, beta, out);
}

// round 5
// speedup vs baseline: 5.2484x; 1.6371x over previous
#include <cuda_runtime.h>
#include <cuda_fp16.h>

#define Bn 16
#define Cn 1024
#define Tn 2048
#define Dn 512
#define Sn (Tn / 2)
#define EPSf 1e-5f

typedef unsigned int u32;

// ---------------- scratch (static device arrays) ----------------
__device__ __align__(16) __half g_xt [(size_t)Bn * Tn * Cn];   // x^T (B,T,C)
__device__ __align__(16) __half g_wq [Dn * Cn];
__device__ __align__(16) __half g_wk [Dn * Cn];
__device__ __align__(16) __half g_wv [Dn * Cn];
__device__ __align__(16) __half g_wo [Cn * Dn];
__device__ __align__(16) __half g_qt [(size_t)Bn * Tn * Dn];   // Q^T (B,T,D)
__device__ __align__(16) __half g_kp [(size_t)Bn * Dn * Sn];   // pooled K
__device__ __align__(16) __half g_vp [(size_t)Bn * Dn * Sn];   // pooled V
__device__ __align__(16) __half g_m  [(size_t)Bn * Dn * Dn];   // M = Vp Kp^T
__device__ __align__(16) __half g_ot [(size_t)Bn * Tn * Dn];   // out^T (B,T,D)
__device__ __align__(16) __half g_y  [(size_t)Bn * Cn * Tn];   // pre-BN y (fp16)
__device__ float g_mean[Cn];
__device__ float g_istd[Cn];

// ---------------- PTX helpers ----------------
__device__ __forceinline__ u32 smem_u32(const void* p) {
    u32 a;
    asm("{ .reg .u64 t; cvta.to.shared.u64 t, %1; cvt.u32.u64 %0, t; }" : "=r"(a) : "l"(p));
    return a;
}

#define CPA16(dst, src) \
    asm volatile("cp.async.cg.shared.global [%0], [%1], 16;" :: "r"(dst), "l"(src) : "memory")
#define CP_COMMIT() asm volatile("cp.async.commit_group;" ::: "memory")

#define LDSM4(r, a) \
    asm volatile("ldmatrix.sync.aligned.m8n8.x4.shared.b16 {%0,%1,%2,%3}, [%4];" \
        : "=r"((r)[0]), "=r"((r)[1]), "=r"((r)[2]), "=r"((r)[3]) : "r"(a))

#define MMA_F16(d, a, b0, b1) \
    asm volatile("mma.sync.aligned.m16n8k16.row.col.f32.f16.f16.f32 " \
        "{%0,%1,%2,%3}, {%4,%5,%6,%7}, {%8,%9}, {%0,%1,%2,%3};" \
        : "+f"((d)[0]), "+f"((d)[1]), "+f"((d)[2]), "+f"((d)[3]) \
        : "r"((a)[0]), "r"((a)[1]), "r"((a)[2]), "r"((a)[3]), "r"(b0), "r"(b1))

__device__ __forceinline__ u32 pack_h2(float v0, float v1) {
    __half h0 = __float2half_rn(v0), h1 = __float2half_rn(v1);
    return (u32)__half_as_ushort(h0) | ((u32)__half_as_ushort(h1) << 16);
}

// ---------------- warp-MMA plain-fp16 GEMM ----------------
// C(M,N) = alpha * A(M,K) * Bt(N,K)^T + bias
// A, Bt row-major K-major fp16; fp32 accumulate.
// BIAS: 0 none, 1 per-row, 2 per-col.
// OMODE: 1 fp16; 3 pool2 along N -> fp16 (N halves).
// CTA 128x128, BK=32, 8 warps (32x64), cp.async double buffer,
// 80B-padded smem rows (conflict-free ldmatrix).
#define TILE_B 10240           // 128 rows * 80 B
#define BUF_B  (2 * TILE_B)    // A, B
#define SMEM_B (2 * BUF_B)     // double buffered = 40960

template <int BIAS, int OMODE>
__global__ void __launch_bounds__(256) wgemm(
    const __half* __restrict__ A, const __half* __restrict__ Bt,
    const float* __restrict__ bias,
    __half* __restrict__ Ch,
    int M, int N, int K, float alpha,
    size_t sA, size_t sB, size_t sC)
{
    extern __shared__ __align__(128) char smem[];
    const u32 sbase = smem_u32(smem);
    const int tid = threadIdx.x;
    const int lane = tid & 31;
    const int warp = tid >> 5;
    const int wr = warp >> 1;       // 0..3 -> 32-row block
    const int wc = warp & 1;        // 0..1 -> 64-col block

    A  += (size_t)blockIdx.z * sA;
    Bt += (size_t)blockIdx.z * sB;
    const size_t coff = (size_t)blockIdx.z * sC;

    const int brow = blockIdx.y * 128;
    const int bcol = blockIdx.x * 128;
    const int KT = K >> 5;

    const __half* srcs[2] = {A, Bt};

    auto load_tiles = [&](int buf, int kt) {
        const int k0 = kt << 5;
#pragma unroll
        for (int tile = 0; tile < 2; tile++) {
            const __half* src = srcs[tile];
            const int rowbase = tile ? bcol : brow;
            const u32 db = sbase + (u32)buf * BUF_B + (u32)tile * TILE_B;
#pragma unroll
            for (int it = 0; it < 2; it++) {
                const int idx = tid + it * 256;
                const int r = idx >> 2, ch = idx & 3;
                const __half* g = src + (size_t)(rowbase + r) * K + k0 + ch * 8;
                CPA16(db + (u32)(r * 80 + ch * 16), g);
            }
        }
    };

    float acc[2][8][4];
#pragma unroll
    for (int i = 0; i < 2; i++)
#pragma unroll
        for (int j = 0; j < 8; j++)
#pragma unroll
            for (int q = 0; q < 4; q++) acc[i][j][q] = 0.f;

    load_tiles(0, 0);
    CP_COMMIT();

    const u32 rowoff = (u32)(((lane >> 3) & 1) * 8 + (lane & 7));
    const u32 chsel  = (u32)(lane >> 4);

    for (int kt = 0; kt < KT; kt++) {
        const int buf = kt & 1;
        if (kt + 1 < KT) {
            load_tiles(buf ^ 1, kt + 1);
            CP_COMMIT();
            asm volatile("cp.async.wait_group 1;" ::: "memory");
        } else {
            asm volatile("cp.async.wait_group 0;" ::: "memory");
        }
        __syncthreads();

        const u32 at = sbase + (u32)buf * BUF_B;
#pragma unroll
        for (int ks = 0; ks < 2; ks++) {
            const u32 choff = (u32)(ks * 2 + chsel) * 16;
            u32 ar[2][4];
#pragma unroll
            for (int i = 0; i < 2; i++) {
                const u32 ad = at + (u32)(wr * 32 + i * 16 + rowoff) * 80 + choff;
                LDSM4(ar[i], ad);
            }
            u32 br[4][4];
#pragma unroll
            for (int j4 = 0; j4 < 4; j4++) {
                const u32 bd = at + TILE_B + (u32)(wc * 64 + j4 * 16 + rowoff) * 80 + choff;
                LDSM4(br[j4], bd);
            }
#pragma unroll
            for (int i = 0; i < 2; i++)
#pragma unroll
                for (int j = 0; j < 8; j++) {
                    const int j4 = j >> 1, h = j & 1;
                    MMA_F16(acc[i][j], ar[i], br[j4][h], br[j4][h + 2]);
                }
        }
        __syncthreads();
    }

    // ---------------- epilogue ----------------
    const int r0 = brow + wr * 32 + (lane >> 2);
    const int c0l = wc * 64 + (lane & 3) * 2;
#pragma unroll
    for (int i = 0; i < 2; i++) {
#pragma unroll
        for (int half = 0; half < 2; half++) {
            const int row = r0 + i * 16 + half * 8;
            const float badd = (BIAS == 1) ? bias[row] : 0.f;
#pragma unroll
            for (int j = 0; j < 8; j++) {
                const int col = bcol + c0l + j * 8;
                float v0 = alpha * acc[i][j][half * 2 + 0] + badd;
                float v1 = alpha * acc[i][j][half * 2 + 1] + badd;
                if (BIAS == 2) { v0 += bias[col]; v1 += bias[col + 1]; }
                if (OMODE == 1) {
                    *(u32*)(Ch + coff + (size_t)row * N + col) = pack_h2(v0, v1);
                } else { // OMODE == 3: maxpool pairs of adjacent cols
                    Ch[coff + (size_t)row * (N >> 1) + (col >> 1)] =
                        __float2half_rn(fmaxf(v0, v1));
                }
            }
        }
    }
}

// ---------------- x (B,C,T) fp32 -> x^T (B,T,C) fp16 ----------------
__global__ void xtrans(const float* __restrict__ x, __half* __restrict__ o)
{
    __shared__ float s[32][33];
    const int b = blockIdx.z;
    const int c0 = blockIdx.y * 32;
    const int t0 = blockIdx.x * 32;
    const int tid = threadIdx.x;
    for (int i = tid; i < 1024; i += 256) {
        const int r = i >> 5, cc = i & 31;
        s[r][cc] = x[((size_t)b * Cn + c0 + r) * Tn + t0 + cc];
    }
    __syncthreads();
    for (int i = tid; i < 512; i += 256) {
        const int r = i >> 4, cp = (i & 15) * 2;
        const size_t oo = ((size_t)b * Tn + t0 + r) * Cn + c0 + cp;
        *(u32*)(o + oo) = pack_h2(s[cp][r], s[cp + 1][r]);
    }
}

// ---------------- fp32 -> fp16 (weights) ----------------
__global__ void wconv(const float* __restrict__ in, __half* __restrict__ o, size_t n4)
{
    const size_t i = (size_t)blockIdx.x * blockDim.x + threadIdx.x;
    if (i >= n4) return;
    const float4 v = ((const float4*)in)[i];
    ((uint2*)o)[i] = make_uint2(pack_h2(v.x, v.y), pack_h2(v.z, v.w));
}

// ---------------- BN batch stats (fp16 y) ----------------
__global__ void bn_stats(const __half* __restrict__ y,
                         float* __restrict__ mean, float* __restrict__ istd)
{
    const int c = blockIdx.x;
    float s = 0.f, s2 = 0.f;
    for (int b = 0; b < Bn; b++) {
        const __half* row = y + ((size_t)b * Cn + c) * Tn;
        for (int t = threadIdx.x * 8; t < Tn; t += blockDim.x * 8) {
            const uint4 u = *(const uint4*)(row + t);
            const u32 w[4] = {u.x, u.y, u.z, u.w};
#pragma unroll
            for (int q = 0; q < 4; q++) {
                const float2 f = __half22float2(*(const __half2*)&w[q]);
                s  += f.x + f.y;
                s2 += f.x * f.x + f.y * f.y;
            }
        }
    }
#pragma unroll
    for (int o = 16; o > 0; o >>= 1) {
        s  += __shfl_down_sync(0xffffffffu, s,  o);
        s2 += __shfl_down_sync(0xffffffffu, s2, o);
    }
    __shared__ float ss[32], ss2[32];
    const int lane = threadIdx.x & 31, w = threadIdx.x >> 5;
    if (lane == 0) { ss[w] = s; ss2[w] = s2; }
    __syncthreads();
    if (w == 0) {
        const int nw = blockDim.x >> 5;
        s  = lane < nw ? ss[lane]  : 0.f;
        s2 = lane < nw ? ss2[lane] : 0.f;
#pragma unroll
        for (int o = 16; o > 0; o >>= 1) {
            s  += __shfl_down_sync(0xffffffffu, s,  o);
            s2 += __shfl_down_sync(0xffffffffu, s2, o);
        }
        if (lane == 0) {
            const float n = (float)(Bn * Tn);
            const float m = s / n;
            mean[c] = m;
            istd[c] = rsqrtf(s2 / n - m * m + EPSf);
        }
    }
}

// ---------------- BN apply + residual ----------------
__global__ void bn_apply(const __half* __restrict__ y, const float* __restrict__ x,
                         const float* __restrict__ mean, const float* __restrict__ istd,
                         const float* __restrict__ gamma, const float* __restrict__ beta,
                         float* __restrict__ out)
{
    const size_t i4 = ((size_t)blockIdx.x * blockDim.x + threadIdx.x) * 4;
    const size_t total = (size_t)Bn * Cn * Tn;
    if (i4 >= total) return;
    const int c = (int)((i4 / Tn) % Cn);
    const float g = gamma[c] * istd[c];
    const float m = mean[c];
    const float bt = beta[c];
    const uint2 u = *(const uint2*)(y + i4);
    const float2 f0 = __half22float2(*(const __half2*)&u.x);
    const float2 f1 = __half22float2(*(const __half2*)&u.y);
    const float4 xv = *(const float4*)(x + i4);
    float4 o;
    o.x = g * (f0.x - m) + bt + xv.x;
    o.y = g * (f0.y - m) + bt + xv.y;
    o.z = g * (f1.x - m) + bt + xv.z;
    o.w = g * (f1.y - m) + bt + xv.w;
    *(float4*)(out + i4) = o;
}

extern "C" void kernel_launch(void* const* d_in, const int* in_sizes, int n_in,
                              void* d_out, int out_size)
{
    const float* x     = (const float*)d_in[0];
    const float* Wq    = (const float*)d_in[1];
    const float* bq    = (const float*)d_in[2];
    const float* Wk    = (const float*)d_in[3];
    const float* bk    = (const float*)d_in[4];
    const float* Wv    = (const float*)d_in[5];
    const float* bv    = (const float*)d_in[6];
    const float* Wo    = (const float*)d_in[7];
    const float* bo    = (const float*)d_in[8];
    const float* gamma = (const float*)d_in[9];
    const float* beta  = (const float*)d_in[10];
    float* out = (float*)d_out;

    __half *xt, *wq, *wk, *wv, *wo, *qt, *kp, *vp, *mm, *ot, *yp;
    float *mean, *istd;
    cudaGetSymbolAddress((void**)&xt, g_xt);
    cudaGetSymbolAddress((void**)&wq, g_wq);
    cudaGetSymbolAddress((void**)&wk, g_wk);
    cudaGetSymbolAddress((void**)&wv, g_wv);
    cudaGetSymbolAddress((void**)&wo, g_wo);
    cudaGetSymbolAddress((void**)&qt, g_qt);
    cudaGetSymbolAddress((void**)&kp, g_kp);
    cudaGetSymbolAddress((void**)&vp, g_vp);
    cudaGetSymbolAddress((void**)&mm, g_m);
    cudaGetSymbolAddress((void**)&ot, g_ot);
    cudaGetSymbolAddress((void**)&yp, g_y);
    cudaGetSymbolAddress((void**)&mean, g_mean);
    cudaGetSymbolAddress((void**)&istd, g_istd);

    cudaFuncSetAttribute(wgemm<1, 3>, cudaFuncAttributeMaxDynamicSharedMemorySize, SMEM_B);
    cudaFuncSetAttribute(wgemm<2, 1>, cudaFuncAttributeMaxDynamicSharedMemorySize, SMEM_B);
    cudaFuncSetAttribute(wgemm<0, 1>, cudaFuncAttributeMaxDynamicSharedMemorySize, SMEM_B);
    cudaFuncSetAttribute(wgemm<1, 1>, cudaFuncAttributeMaxDynamicSharedMemorySize, SMEM_B);

    // conversions
    xtrans<<<dim3(Tn / 32, Cn / 32, Bn), 256>>>(x, xt);
    const size_t nw4 = (size_t)Dn * Cn / 4;
    wconv<<<(unsigned)((nw4 + 255) / 256), 256>>>(Wq, wq, nw4);
    wconv<<<(unsigned)((nw4 + 255) / 256), 256>>>(Wk, wk, nw4);
    wconv<<<(unsigned)((nw4 + 255) / 256), 256>>>(Wv, wv, nw4);
    wconv<<<(unsigned)((nw4 + 255) / 256), 256>>>(Wo, wo, nw4);

    const size_t sTC = (size_t)Tn * Cn;
    const size_t sTD = (size_t)Tn * Dn;
    const size_t sDS = (size_t)Dn * Sn;
    const size_t sDD = (size_t)Dn * Dn;
    const size_t sCT = (size_t)Cn * Tn;

    // K proj + fused pool: Kp(D,S) = pool2(Wk x + bk); A=Wk(D,C), Bt=xT(T,C)
    const dim3 gkv(Tn / 128, Dn / 128, Bn);
    wgemm<1, 3><<<gkv, 256, SMEM_B>>>(wk, xt, bk, kp, Dn, Tn, Cn, 1.f, 0, sTC, sDS);
    // V proj + fused pool
    wgemm<1, 3><<<gkv, 256, SMEM_B>>>(wv, xt, bv, vp, Dn, Tn, Cn, 1.f, 0, sTC, sDS);

    // Q^T(T,D) = xT Wq^T + bq(col); A=xT(T,C), Bt=Wq(D,C)
    const dim3 gq(Dn / 128, Tn / 128, Bn);
    wgemm<2, 1><<<gq, 256, SMEM_B>>>(xt, wq, bq, qt, Tn, Dn, Cn, 1.f, sTC, 0, sTD);

    // M(D,D) = Vp Kp^T; A=Vp(D,S), Bt=Kp(D,S)
    const dim3 gm(Dn / 128, Dn / 128, Bn);
    wgemm<0, 1><<<gm, 256, SMEM_B>>>(vp, kp, nullptr, mm, Dn, Dn, Sn, 1.f, sDS, sDS, sDD);

    // out^T(T,D) = (1/T) Q^T M^T; A=Q^T(T,D), Bt=M(D,D)
    const dim3 go(Dn / 128, Tn / 128, Bn);
    wgemm<0, 1><<<go, 256, SMEM_B>>>(qt, mm, nullptr, ot, Tn, Dn, Dn, 1.f / (float)Tn,
                                     sTD, sDD, sTD);

    // y(C,T) = Wo out + bo; A=Wo(C,D), Bt=out^T(T,D) -> fp16 y
    const dim3 gy(Tn / 128, Cn / 128, Bn);
    wgemm<1, 1><<<gy, 256, SMEM_B>>>(wo, ot, bo, yp, Cn, Tn, Dn, 1.f, 0, sTD, sCT);

    // BatchNorm + residual
    bn_stats<<<Cn, 256>>>(yp, mean, istd);
    const size_t total4 = (size_t)Bn * Cn * Tn / 4;
    bn_apply<<<(unsigned)((total4 + 255) / 256), 256>>>(yp, x, mean, istd, gamma, beta, out);
}

// round 6
// speedup vs baseline: 5.3542x; 1.0201x over previous
#include <cuda_runtime.h>
#include <cuda_fp16.h>

#define Bn 16
#define Cn 1024
#define Tn 2048
#define Dn 512
#define Sn (Tn / 2)
#define EPSf 1e-5f

typedef unsigned int u32;

// ---------------- scratch (static device arrays) ----------------
__device__ __align__(16) __half g_xt [(size_t)Bn * Tn * Cn];        // x^T (B,T,C)
__device__ __align__(16) __half g_wq [Dn * Cn];
__device__ __align__(16) __half g_wkv[2 * Dn * Cn];                 // [Wk; Wv] stacked
__device__ __align__(16) __half g_wo [Cn * Dn];
__device__ __align__(16) __half g_qt [(size_t)Bn * Tn * Dn];        // Q^T (B,T,D)
__device__ __align__(16) __half g_kv [(size_t)Bn * 2 * Dn * Sn];    // [Kp; Vp] pooled (B,2D,S)
__device__ __align__(16) __half g_mt [(size_t)Bn * Dn * Dn];        // Mt = Kp Vp^T
__device__ __align__(16) __half g_p  [(size_t)Bn * Cn * Dn];        // P = Wo M
__device__ __align__(16) __half g_y  [(size_t)Bn * Cn * Tn];        // pre-BN y (fp16)
__device__ float g_bkv[2 * Dn];
__device__ float g_mean[Cn];
__device__ float g_istd[Cn];

// ---------------- PTX helpers ----------------
__device__ __forceinline__ u32 smem_u32(const void* p) {
    u32 a;
    asm("{ .reg .u64 t; cvta.to.shared.u64 t, %1; cvt.u32.u64 %0, t; }" : "=r"(a) : "l"(p));
    return a;
}

#define CPA16(dst, src) \
    asm volatile("cp.async.cg.shared.global [%0], [%1], 16;" :: "r"(dst), "l"(src) : "memory")
#define CP_COMMIT() asm volatile("cp.async.commit_group;" ::: "memory")

#define LDSM4(r, a) \
    asm volatile("ldmatrix.sync.aligned.m8n8.x4.shared.b16 {%0,%1,%2,%3}, [%4];" \
        : "=r"((r)[0]), "=r"((r)[1]), "=r"((r)[2]), "=r"((r)[3]) : "r"(a))

#define MMA_F16(d, a, b0, b1) \
    asm volatile("mma.sync.aligned.m16n8k16.row.col.f32.f16.f16.f32 " \
        "{%0,%1,%2,%3}, {%4,%5,%6,%7}, {%8,%9}, {%0,%1,%2,%3};" \
        : "+f"((d)[0]), "+f"((d)[1]), "+f"((d)[2]), "+f"((d)[3]) \
        : "r"((a)[0]), "r"((a)[1]), "r"((a)[2]), "r"((a)[3]), "r"(b0), "r"(b1))

__device__ __forceinline__ u32 pack_h2(float v0, float v1) {
    __half h0 = __float2half_rn(v0), h1 = __float2half_rn(v1);
    return (u32)__half_as_ushort(h0) | ((u32)__half_as_ushort(h1) << 16);
}

// ---------------- warp-MMA plain-fp16 GEMM, 3-stage pipeline ----------------
// C(M,N) = alpha * A(M,K) * Bt(N,K)^T + bias
// A, Bt row-major K-major fp16; fp32 accumulate.
// BIAS: 0 none, 1 per-row, 2 per-col.
// OMODE: 1 fp16; 3 pool2 along N -> fp16 (N halves).
// CTA 128x128, BK=32, 8 warps (32x64), cp.async TRIPLE buffer,
// one __syncthreads per k-iter, 80B-padded smem rows.
#define TILE_B 10240           // 128 rows * 80 B
#define BUF_B  (2 * TILE_B)    // A, B
#define SMEM_B (3 * BUF_B)     // triple buffered = 61440

template <int BIAS, int OMODE>
__global__ void __launch_bounds__(256) wgemm(
    const __half* __restrict__ A, const __half* __restrict__ Bt,
    const float* __restrict__ bias,
    __half* __restrict__ Ch,
    int M, int N, int K, float alpha,
    size_t sA, size_t sB, size_t sC)
{
    extern __shared__ __align__(128) char smem[];
    const u32 sbase = smem_u32(smem);
    const int tid = threadIdx.x;
    const int lane = tid & 31;
    const int warp = tid >> 5;
    const int wr = warp >> 1;       // 0..3 -> 32-row block
    const int wc = warp & 1;        // 0..1 -> 64-col block

    A  += (size_t)blockIdx.z * sA;
    Bt += (size_t)blockIdx.z * sB;
    const size_t coff = (size_t)blockIdx.z * sC;

    const int brow = blockIdx.y * 128;
    const int bcol = blockIdx.x * 128;
    const int KT = K >> 5;

    const __half* srcs[2] = {A, Bt};

    auto load_tiles = [&](int buf, int kt) {
        const int k0 = kt << 5;
#pragma unroll
        for (int tile = 0; tile < 2; tile++) {
            const __half* src = srcs[tile];
            const int rowbase = tile ? bcol : brow;
            const u32 db = sbase + (u32)buf * BUF_B + (u32)tile * TILE_B;
#pragma unroll
            for (int it = 0; it < 2; it++) {
                const int idx = tid + it * 256;
                const int r = idx >> 2, ch = idx & 3;
                const __half* g = src + (size_t)(rowbase + r) * K + k0 + ch * 8;
                CPA16(db + (u32)(r * 80 + ch * 16), g);
            }
        }
    };

    float acc[2][8][4];
#pragma unroll
    for (int i = 0; i < 2; i++)
#pragma unroll
        for (int j = 0; j < 8; j++)
#pragma unroll
            for (int q = 0; q < 4; q++) acc[i][j][q] = 0.f;

    // 3-stage prologue
    load_tiles(0, 0);
    CP_COMMIT();
    load_tiles(1, 1);
    CP_COMMIT();

    const u32 rowoff = (u32)(((lane >> 3) & 1) * 8 + (lane & 7));
    const u32 chsel  = (u32)(lane >> 4);

    int buf = 0;
    for (int kt = 0; kt < KT; kt++) {
        asm volatile("cp.async.wait_group 1;" ::: "memory");
        __syncthreads();   // tile kt visible to all; buffer (kt-1)%3 free for reuse

        // prefetch kt+2 into buffer (kt+2)%3 == (kt-1)%3 ... (3 buffers)
        if (kt + 2 < KT) {
            int nb = buf + 2; if (nb >= 3) nb -= 3;
            load_tiles(nb, kt + 2);
        }
        CP_COMMIT();   // commit every iter (possibly empty) to keep group counts aligned

        const u32 at = sbase + (u32)buf * BUF_B;
#pragma unroll
        for (int ks = 0; ks < 2; ks++) {
            const u32 choff = (u32)(ks * 2 + chsel) * 16;
            u32 ar[2][4];
#pragma unroll
            for (int i = 0; i < 2; i++) {
                const u32 ad = at + (u32)(wr * 32 + i * 16 + rowoff) * 80 + choff;
                LDSM4(ar[i], ad);
            }
            u32 br[4][4];
#pragma unroll
            for (int j4 = 0; j4 < 4; j4++) {
                const u32 bd = at + TILE_B + (u32)(wc * 64 + j4 * 16 + rowoff) * 80 + choff;
                LDSM4(br[j4], bd);
            }
#pragma unroll
            for (int i = 0; i < 2; i++)
#pragma unroll
                for (int j = 0; j < 8; j++) {
                    const int j4 = j >> 1, h = j & 1;
                    MMA_F16(acc[i][j], ar[i], br[j4][h], br[j4][h + 2]);
                }
        }
        if (++buf == 3) buf = 0;
    }

    // ---------------- epilogue ----------------
    const int r0 = brow + wr * 32 + (lane >> 2);
    const int c0l = wc * 64 + (lane & 3) * 2;
#pragma unroll
    for (int i = 0; i < 2; i++) {
#pragma unroll
        for (int half = 0; half < 2; half++) {
            const int row = r0 + i * 16 + half * 8;
            const float badd = (BIAS == 1) ? bias[row] : 0.f;
#pragma unroll
            for (int j = 0; j < 8; j++) {
                const int col = bcol + c0l + j * 8;
                float v0 = alpha * acc[i][j][half * 2 + 0] + badd;
                float v1 = alpha * acc[i][j][half * 2 + 1] + badd;
                if (BIAS == 2) { v0 += bias[col]; v1 += bias[col + 1]; }
                if (OMODE == 1) {
                    *(u32*)(Ch + coff + (size_t)row * N + col) = pack_h2(v0, v1);
                } else { // OMODE == 3: maxpool pairs of adjacent cols
                    Ch[coff + (size_t)row * (N >> 1) + (col >> 1)] =
                        __float2half_rn(fmaxf(v0, v1));
                }
            }
        }
    }
}

// ---------------- x (B,C,T) fp32 -> x^T (B,T,C) fp16 ----------------
__global__ void xtrans(const float* __restrict__ x, __half* __restrict__ o)
{
    __shared__ float s[32][33];
    const int b = blockIdx.z;
    const int c0 = blockIdx.y * 32;
    const int t0 = blockIdx.x * 32;
    const int tid = threadIdx.x;
    for (int i = tid; i < 1024; i += 256) {
        const int r = i >> 5, cc = i & 31;
        s[r][cc] = x[((size_t)b * Cn + c0 + r) * Tn + t0 + cc];
    }
    __syncthreads();
    for (int i = tid; i < 512; i += 256) {
        const int r = i >> 4, cp = (i & 15) * 2;
        const size_t oo = ((size_t)b * Tn + t0 + r) * Cn + c0 + cp;
        *(u32*)(o + oo) = pack_h2(s[cp][r], s[cp + 1][r]);
    }
}

// ---------------- 4x weight fp32 -> fp16 (one launch) ----------------
__global__ void wconv4(const float* __restrict__ w0, const float* __restrict__ w1,
                       const float* __restrict__ w2, const float* __restrict__ w3,
                       __half* __restrict__ o0, __half* __restrict__ o1,
                       __half* __restrict__ o2, __half* __restrict__ o3, size_t n4)
{
    const size_t i = (size_t)blockIdx.x * blockDim.x + threadIdx.x;
    if (i >= n4) return;
    const float* srcs[4] = {w0, w1, w2, w3};
    __half* dsts[4] = {o0, o1, o2, o3};
    const float4 v = ((const float4*)srcs[blockIdx.y])[i];
    ((uint2*)dsts[blockIdx.y])[i] = make_uint2(pack_h2(v.x, v.y), pack_h2(v.z, v.w));
}

// ---------------- stack bk|bv into one bias vector ----------------
__global__ void packbias(const float* __restrict__ bk, const float* __restrict__ bv,
                         float* __restrict__ o)
{
    const int i = blockIdx.x * blockDim.x + threadIdx.x;
    if (i < Dn) o[i] = bk[i];
    else if (i < 2 * Dn) o[i] = bv[i - Dn];
}

// ---------------- BN batch stats (fp16 y) ----------------
__global__ void bn_stats(const __half* __restrict__ y,
                         float* __restrict__ mean, float* __restrict__ istd)
{
    const int c = blockIdx.x;
    float s = 0.f, s2 = 0.f;
    for (int b = 0; b < Bn; b++) {
        const __half* row = y + ((size_t)b * Cn + c) * Tn;
        for (int t = threadIdx.x * 8; t < Tn; t += blockDim.x * 8) {
            const uint4 u = *(const uint4*)(row + t);
            const u32 w[4] = {u.x, u.y, u.z, u.w};
#pragma unroll
            for (int q = 0; q < 4; q++) {
                const float2 f = __half22float2(*(const __half2*)&w[q]);
                s  += f.x + f.y;
                s2 += f.x * f.x + f.y * f.y;
            }
        }
    }
#pragma unroll
    for (int o = 16; o > 0; o >>= 1) {
        s  += __shfl_down_sync(0xffffffffu, s,  o);
        s2 += __shfl_down_sync(0xffffffffu, s2, o);
    }
    __shared__ float ss[32], ss2[32];
    const int lane = threadIdx.x & 31, w = threadIdx.x >> 5;
    if (lane == 0) { ss[w] = s; ss2[w] = s2; }
    __syncthreads();
    if (w == 0) {
        const int nw = blockDim.x >> 5;
        s  = lane < nw ? ss[lane]  : 0.f;
        s2 = lane < nw ? ss2[lane] : 0.f;
#pragma unroll
        for (int o = 16; o > 0; o >>= 1) {
            s  += __shfl_down_sync(0xffffffffu, s,  o);
            s2 += __shfl_down_sync(0xffffffffu, s2, o);
        }
        if (lane == 0) {
            const float n = (float)(Bn * Tn);
            const float m = s / n;
            mean[c] = m;
            istd[c] = rsqrtf(s2 / n - m * m + EPSf);
        }
    }
}

// ---------------- BN apply + residual ----------------
__global__ void bn_apply(const __half* __restrict__ y, const float* __restrict__ x,
                         const float* __restrict__ mean, const float* __restrict__ istd,
                         const float* __restrict__ gamma, const float* __restrict__ beta,
                         float* __restrict__ out)
{
    const size_t i4 = ((size_t)blockIdx.x * blockDim.x + threadIdx.x) * 4;
    const size_t total = (size_t)Bn * Cn * Tn;
    if (i4 >= total) return;
    const int c = (int)((i4 / Tn) % Cn);
    const float g = gamma[c] * istd[c];
    const float m = mean[c];
    const float bt = beta[c];
    const uint2 u = *(const uint2*)(y + i4);
    const float2 f0 = __half22float2(*(const __half2*)&u.x);
    const float2 f1 = __half22float2(*(const __half2*)&u.y);
    const float4 xv = *(const float4*)(x + i4);
    float4 o;
    o.x = g * (f0.x - m) + bt + xv.x;
    o.y = g * (f0.y - m) + bt + xv.y;
    o.z = g * (f1.x - m) + bt + xv.z;
    o.w = g * (f1.y - m) + bt + xv.w;
    *(float4*)(out + i4) = o;
}

extern "C" void kernel_launch(void* const* d_in, const int* in_sizes, int n_in,
                              void* d_out, int out_size)
{
    const float* x     = (const float*)d_in[0];
    const float* Wq    = (const float*)d_in[1];
    const float* bq    = (const float*)d_in[2];
    const float* Wk    = (const float*)d_in[3];
    const float* bk    = (const float*)d_in[4];
    const float* Wv    = (const float*)d_in[5];
    const float* bv    = (const float*)d_in[6];
    const float* Wo    = (const float*)d_in[7];
    const float* bo    = (const float*)d_in[8];
    const float* gamma = (const float*)d_in[9];
    const float* beta  = (const float*)d_in[10];
    float* out = (float*)d_out;

    __half *xt, *wq, *wkv, *wo, *qt, *kv, *mt, *pp, *yp;
    float *bkv, *mean, *istd;
    cudaGetSymbolAddress((void**)&xt,  g_xt);
    cudaGetSymbolAddress((void**)&wq,  g_wq);
    cudaGetSymbolAddress((void**)&wkv, g_wkv);
    cudaGetSymbolAddress((void**)&wo,  g_wo);
    cudaGetSymbolAddress((void**)&qt,  g_qt);
    cudaGetSymbolAddress((void**)&kv,  g_kv);
    cudaGetSymbolAddress((void**)&mt,  g_mt);
    cudaGetSymbolAddress((void**)&pp,  g_p);
    cudaGetSymbolAddress((void**)&yp,  g_y);
    cudaGetSymbolAddress((void**)&bkv, g_bkv);
    cudaGetSymbolAddress((void**)&mean, g_mean);
    cudaGetSymbolAddress((void**)&istd, g_istd);

    cudaFuncSetAttribute(wgemm<1, 3>, cudaFuncAttributeMaxDynamicSharedMemorySize, SMEM_B);
    cudaFuncSetAttribute(wgemm<2, 1>, cudaFuncAttributeMaxDynamicSharedMemorySize, SMEM_B);
    cudaFuncSetAttribute(wgemm<0, 1>, cudaFuncAttributeMaxDynamicSharedMemorySize, SMEM_B);
    cudaFuncSetAttribute(wgemm<1, 1>, cudaFuncAttributeMaxDynamicSharedMemorySize, SMEM_B);

    // conversions
    xtrans<<<dim3(Tn / 32, Cn / 32, Bn), 256>>>(x, xt);
    const size_t nw4 = (size_t)Dn * Cn / 4;   // per weight tensor
    wconv4<<<dim3((unsigned)((nw4 + 255) / 256), 4), 256>>>(
        Wk, Wv, Wq, Wo, wkv, wkv + (size_t)Dn * Cn, wq, wo, nw4);
    packbias<<<4, 256>>>(bk, bv, bkv);

    const size_t sTC  = (size_t)Tn * Cn;
    const size_t sTD  = (size_t)Tn * Dn;
    const size_t s2DS = (size_t)2 * Dn * Sn;
    const size_t sDD  = (size_t)Dn * Dn;
    const size_t sCD  = (size_t)Cn * Dn;
    const size_t sCT  = (size_t)Cn * Tn;

    // KV proj + fused pool: [Kp;Vp](2D,S) = pool2(Wkv x + bkv)
    const dim3 gkv(Tn / 128, 2 * Dn / 128, Bn);
    wgemm<1, 3><<<gkv, 256, SMEM_B>>>(wkv, xt, bkv, kv, 2 * Dn, Tn, Cn, 1.f, 0, sTC, s2DS);

    // Q^T(T,D) = xT Wq^T + bq(col)
    const dim3 gq(Dn / 128, Tn / 128, Bn);
    wgemm<2, 1><<<gq, 256, SMEM_B>>>(xt, wq, bq, qt, Tn, Dn, Cn, 1.f, sTC, 0, sTD);

    // Mt(D,D) = Kp Vp^T  (= M^T); A=Kp rows 0..D-1 of kv, Bt=Vp rows D..2D-1
    const dim3 gm(Dn / 128, Dn / 128, Bn);
    wgemm<0, 1><<<gm, 256, SMEM_B>>>(kv, kv + (size_t)Dn * Sn, nullptr, mt,
                                     Dn, Dn, Sn, 1.f, s2DS, s2DS, sDD);

    // P(C,D) = Wo M = Wo Mt^T; A=Wo(C,D), Bt=Mt(D,D)
    const dim3 gp(Dn / 128, Cn / 128, Bn);
    wgemm<0, 1><<<gp, 256, SMEM_B>>>(wo, mt, nullptr, pp, Cn, Dn, Dn, 1.f, 0, sDD, sCD);

    // y(C,T) = (1/T) P Q + bo; A=P(C,D), Bt=Q^T(T,D)
    const dim3 gy(Tn / 128, Cn / 128, Bn);
    wgemm<1, 1><<<gy, 256, SMEM_B>>>(pp, qt, bo, yp, Cn, Tn, Dn, 1.f / (float)Tn,
                                     sCD, sTD, sCT);

    // BatchNorm + residual
    bn_stats<<<Cn, 256>>>(yp, mean, istd);
    const size_t total4 = (size_t)Bn * Cn * Tn / 4;
    bn_apply<<<(unsigned)((total4 + 255) / 256), 256>>>(yp, x, mean, istd, gamma, beta, out);
}

// round 7
// speedup vs baseline: 5.7926x; 1.0819x over previous
#include <cuda_runtime.h>
#include <cuda_fp16.h>

#define Bn 16
#define Cn 1024
#define Tn 2048
#define Dn 512
#define Sn (Tn / 2)
#define EPSf 1e-5f

typedef unsigned int u32;

// ---------------- scratch (static device arrays) ----------------
__device__ __align__(16) __half g_xt [(size_t)Bn * Tn * Cn];        // x^T (B,T,C)
__device__ __align__(16) __half g_wq [Dn * Cn];
__device__ __align__(16) __half g_wkv[2 * Dn * Cn];                 // [Wk; Wv] stacked
__device__ __align__(16) __half g_wo [Cn * Dn];
__device__ __align__(16) __half g_qt [(size_t)Bn * Tn * Dn];        // Q^T (B,T,D)
__device__ __align__(16) __half g_kv [(size_t)Bn * 2 * Dn * Sn];    // [Kp; Vp] pooled (B,2D,S)
__device__ __align__(16) __half g_mt [(size_t)Bn * Dn * Dn];        // Mt = Kp Vp^T
__device__ __align__(16) __half g_p  [(size_t)Bn * Cn * Dn];        // P = Wo M
__device__ __align__(16) __half g_y  [(size_t)Bn * Cn * Tn];        // pre-BN y (fp16)
__device__ float g_bkv[2 * Dn];
__device__ float g_mean[Cn];
__device__ float g_istd[Cn];

// ---------------- PTX helpers ----------------
__device__ __forceinline__ u32 smem_u32(const void* p) {
    u32 a;
    asm("{ .reg .u64 t; cvta.to.shared.u64 t, %1; cvt.u32.u64 %0, t; }" : "=r"(a) : "l"(p));
    return a;
}

#define CPA16(dst, src) \
    asm volatile("cp.async.cg.shared.global [%0], [%1], 16;" :: "r"(dst), "l"(src) : "memory")
#define CP_COMMIT() asm volatile("cp.async.commit_group;" ::: "memory")

#define LDSM4(r, a) \
    asm volatile("ldmatrix.sync.aligned.m8n8.x4.shared.b16 {%0,%1,%2,%3}, [%4];" \
        : "=r"((r)[0]), "=r"((r)[1]), "=r"((r)[2]), "=r"((r)[3]) : "r"(a))

#define MMA_F16(d, a, b0, b1) \
    asm volatile("mma.sync.aligned.m16n8k16.row.col.f32.f16.f16.f32 " \
        "{%0,%1,%2,%3}, {%4,%5,%6,%7}, {%8,%9}, {%0,%1,%2,%3};" \
        : "+f"((d)[0]), "+f"((d)[1]), "+f"((d)[2]), "+f"((d)[3]) \
        : "r"((a)[0]), "r"((a)[1]), "r"((a)[2]), "r"((a)[3]), "r"(b0), "r"(b1))

__device__ __forceinline__ u32 pack_h2(float v0, float v1) {
    __half h0 = __float2half_rn(v0), h1 = __float2half_rn(v1);
    return (u32)__half_as_ushort(h0) | ((u32)__half_as_ushort(h1) << 16);
}

// ---------------- warp-MMA plain-fp16 GEMM, 3-stage pipeline ----------------
// C(M,N) = alpha * A(M,K) * Bt(N,K)^T + bias
// A, Bt row-major K-major fp16; fp32 accumulate.
// BIAS: 0 none, 1 per-row, 2 per-col.
// OMODE: 1 fp16; 3 pool2 along N -> fp16 (N halves).
// CTA 128x128, BK=32, 8 warps (32x64), cp.async TRIPLE buffer,
// one __syncthreads per k-iter, 80B-padded smem rows.
// __launch_bounds__(256, 2): cap 128 regs so TWO CTAs fit per SM (regfile was
// the occupancy limiter at 132 regs -> 1 CTA/SM, tensor pipe 37%).
#define TILE_B 10240           // 128 rows * 80 B
#define BUF_B  (2 * TILE_B)    // A, B
#define SMEM_B (3 * BUF_B)     // triple buffered = 61440

template <int BIAS, int OMODE>
__global__ void __launch_bounds__(256, 2) wgemm(
    const __half* __restrict__ A, const __half* __restrict__ Bt,
    const float* __restrict__ bias,
    __half* __restrict__ Ch,
    int M, int N, int K, float alpha,
    size_t sA, size_t sB, size_t sC)
{
    extern __shared__ __align__(128) char smem[];
    const u32 sbase = smem_u32(smem);
    const int tid = threadIdx.x;
    const int lane = tid & 31;
    const int warp = tid >> 5;
    const int wr = warp >> 1;       // 0..3 -> 32-row block
    const int wc = warp & 1;        // 0..1 -> 64-col block

    A  += (size_t)blockIdx.z * sA;
    Bt += (size_t)blockIdx.z * sB;
    const size_t coff = (size_t)blockIdx.z * sC;

    const int brow = blockIdx.y * 128;
    const int bcol = blockIdx.x * 128;
    const int KT = K >> 5;

    const __half* srcs[2] = {A, Bt};

    auto load_tiles = [&](int buf, int kt) {
        const int k0 = kt << 5;
#pragma unroll
        for (int tile = 0; tile < 2; tile++) {
            const __half* src = srcs[tile];
            const int rowbase = tile ? bcol : brow;
            const u32 db = sbase + (u32)buf * BUF_B + (u32)tile * TILE_B;
#pragma unroll
            for (int it = 0; it < 2; it++) {
                const int idx = tid + it * 256;
                const int r = idx >> 2, ch = idx & 3;
                const __half* g = src + (size_t)(rowbase + r) * K + k0 + ch * 8;
                CPA16(db + (u32)(r * 80 + ch * 16), g);
            }
        }
    };

    float acc[2][8][4];
#pragma unroll
    for (int i = 0; i < 2; i++)
#pragma unroll
        for (int j = 0; j < 8; j++)
#pragma unroll
            for (int q = 0; q < 4; q++) acc[i][j][q] = 0.f;

    // 3-stage prologue
    load_tiles(0, 0);
    CP_COMMIT();
    load_tiles(1, 1);
    CP_COMMIT();

    const u32 rowoff = (u32)(((lane >> 3) & 1) * 8 + (lane & 7));
    const u32 chsel  = (u32)(lane >> 4);

    int buf = 0;
    for (int kt = 0; kt < KT; kt++) {
        asm volatile("cp.async.wait_group 1;" ::: "memory");
        __syncthreads();   // tile kt visible; previous buffer free for reuse

        if (kt + 2 < KT) {
            int nb = buf + 2; if (nb >= 3) nb -= 3;
            load_tiles(nb, kt + 2);
        }
        CP_COMMIT();   // commit every iter to keep group counts aligned

        const u32 at = sbase + (u32)buf * BUF_B;
#pragma unroll
        for (int ks = 0; ks < 2; ks++) {
            const u32 choff = (u32)(ks * 2 + chsel) * 16;
            u32 ar[2][4];
#pragma unroll
            for (int i = 0; i < 2; i++) {
                const u32 ad = at + (u32)(wr * 32 + i * 16 + rowoff) * 80 + choff;
                LDSM4(ar[i], ad);
            }
            u32 br[4][4];
#pragma unroll
            for (int j4 = 0; j4 < 4; j4++) {
                const u32 bd = at + TILE_B + (u32)(wc * 64 + j4 * 16 + rowoff) * 80 + choff;
                LDSM4(br[j4], bd);
            }
#pragma unroll
            for (int i = 0; i < 2; i++)
#pragma unroll
                for (int j = 0; j < 8; j++) {
                    const int j4 = j >> 1, h = j & 1;
                    MMA_F16(acc[i][j], ar[i], br[j4][h], br[j4][h + 2]);
                }
        }
        if (++buf == 3) buf = 0;
    }

    // ---------------- epilogue ----------------
    const int r0 = brow + wr * 32 + (lane >> 2);
    const int c0l = wc * 64 + (lane & 3) * 2;
#pragma unroll
    for (int i = 0; i < 2; i++) {
#pragma unroll
        for (int half = 0; half < 2; half++) {
            const int row = r0 + i * 16 + half * 8;
            const float badd = (BIAS == 1) ? bias[row] : 0.f;
#pragma unroll
            for (int j = 0; j < 8; j++) {
                const int col = bcol + c0l + j * 8;
                float v0 = alpha * acc[i][j][half * 2 + 0] + badd;
                float v1 = alpha * acc[i][j][half * 2 + 1] + badd;
                if (BIAS == 2) { v0 += bias[col]; v1 += bias[col + 1]; }
                if (OMODE == 1) {
                    *(u32*)(Ch + coff + (size_t)row * N + col) = pack_h2(v0, v1);
                } else { // OMODE == 3: maxpool pairs of adjacent cols
                    Ch[coff + (size_t)row * (N >> 1) + (col >> 1)] =
                        __float2half_rn(fmaxf(v0, v1));
                }
            }
        }
    }
}

// ---------------- x (B,C,T) fp32 -> x^T (B,T,C) fp16 ----------------
__global__ void xtrans(const float* __restrict__ x, __half* __restrict__ o)
{
    __shared__ float s[32][33];
    const int b = blockIdx.z;
    const int c0 = blockIdx.y * 32;
    const int t0 = blockIdx.x * 32;
    const int tid = threadIdx.x;
    for (int i = tid; i < 1024; i += 256) {
        const int r = i >> 5, cc = i & 31;
        s[r][cc] = x[((size_t)b * Cn + c0 + r) * Tn + t0 + cc];
    }
    __syncthreads();
    for (int i = tid; i < 512; i += 256) {
        const int r = i >> 4, cp = (i & 15) * 2;
        const size_t oo = ((size_t)b * Tn + t0 + r) * Cn + c0 + cp;
        *(u32*)(o + oo) = pack_h2(s[cp][r], s[cp + 1][r]);
    }
}

// ---------------- 4x weight fp32 -> fp16 (one launch) ----------------
__global__ void wconv4(const float* __restrict__ w0, const float* __restrict__ w1,
                       const float* __restrict__ w2, const float* __restrict__ w3,
                       __half* __restrict__ o0, __half* __restrict__ o1,
                       __half* __restrict__ o2, __half* __restrict__ o3, size_t n4)
{
    const size_t i = (size_t)blockIdx.x * blockDim.x + threadIdx.x;
    if (i >= n4) return;
    const float* srcs[4] = {w0, w1, w2, w3};
    __half* dsts[4] = {o0, o1, o2, o3};
    const float4 v = ((const float4*)srcs[blockIdx.y])[i];
    ((uint2*)dsts[blockIdx.y])[i] = make_uint2(pack_h2(v.x, v.y), pack_h2(v.z, v.w));
}

// ---------------- stack bk|bv into one bias vector ----------------
__global__ void packbias(const float* __restrict__ bk, const float* __restrict__ bv,
                         float* __restrict__ o)
{
    const int i = blockIdx.x * blockDim.x + threadIdx.x;
    if (i < Dn) o[i] = bk[i];
    else if (i < 2 * Dn) o[i] = bv[i - Dn];
}

// ---------------- BN batch stats (fp16 y) ----------------
__global__ void bn_stats(const __half* __restrict__ y,
                         float* __restrict__ mean, float* __restrict__ istd)
{
    const int c = blockIdx.x;
    float s = 0.f, s2 = 0.f;
    for (int b = 0; b < Bn; b++) {
        const __half* row = y + ((size_t)b * Cn + c) * Tn;
        for (int t = threadIdx.x * 8; t < Tn; t += blockDim.x * 8) {
            const uint4 u = *(const uint4*)(row + t);
            const u32 w[4] = {u.x, u.y, u.z, u.w};
#pragma unroll
            for (int q = 0; q < 4; q++) {
                const float2 f = __half22float2(*(const __half2*)&w[q]);
                s  += f.x + f.y;
                s2 += f.x * f.x + f.y * f.y;
            }
        }
    }
#pragma unroll
    for (int o = 16; o > 0; o >>= 1) {
        s  += __shfl_down_sync(0xffffffffu, s,  o);
        s2 += __shfl_down_sync(0xffffffffu, s2, o);
    }
    __shared__ float ss[32], ss2[32];
    const int lane = threadIdx.x & 31, w = threadIdx.x >> 5;
    if (lane == 0) { ss[w] = s; ss2[w] = s2; }
    __syncthreads();
    if (w == 0) {
        const int nw = blockDim.x >> 5;
        s  = lane < nw ? ss[lane]  : 0.f;
        s2 = lane < nw ? ss2[lane] : 0.f;
#pragma unroll
        for (int o = 16; o > 0; o >>= 1) {
            s  += __shfl_down_sync(0xffffffffu, s,  o);
            s2 += __shfl_down_sync(0xffffffffu, s2, o);
        }
        if (lane == 0) {
            const float n = (float)(Bn * Tn);
            const float m = s / n;
            mean[c] = m;
            istd[c] = rsqrtf(s2 / n - m * m + EPSf);
        }
    }
}

// ---------------- BN apply + residual ----------------
__global__ void bn_apply(const __half* __restrict__ y, const float* __restrict__ x,
                         const float* __restrict__ mean, const float* __restrict__ istd,
                         const float* __restrict__ gamma, const float* __restrict__ beta,
                         float* __restrict__ out)
{
    const size_t i4 = ((size_t)blockIdx.x * blockDim.x + threadIdx.x) * 4;
    const size_t total = (size_t)Bn * Cn * Tn;
    if (i4 >= total) return;
    const int c = (int)((i4 / Tn) % Cn);
    const float g = gamma[c] * istd[c];
    const float m = mean[c];
    const float bt = beta[c];
    const uint2 u = *(const uint2*)(y + i4);
    const float2 f0 = __half22float2(*(const __half2*)&u.x);
    const float2 f1 = __half22float2(*(const __half2*)&u.y);
    const float4 xv = *(const float4*)(x + i4);
    float4 o;
    o.x = g * (f0.x - m) + bt + xv.x;
    o.y = g * (f0.y - m) + bt + xv.y;
    o.z = g * (f1.x - m) + bt + xv.z;
    o.w = g * (f1.y - m) + bt + xv.w;
    *(float4*)(out + i4) = o;
}

extern "C" void kernel_launch(void* const* d_in, const int* in_sizes, int n_in,
                              void* d_out, int out_size)
{
    const float* x     = (const float*)d_in[0];
    const float* Wq    = (const float*)d_in[1];
    const float* bq    = (const float*)d_in[2];
    const float* Wk    = (const float*)d_in[3];
    const float* bk    = (const float*)d_in[4];
    const float* Wv    = (const float*)d_in[5];
    const float* bv    = (const float*)d_in[6];
    const float* Wo    = (const float*)d_in[7];
    const float* bo    = (const float*)d_in[8];
    const float* gamma = (const float*)d_in[9];
    const float* beta  = (const float*)d_in[10];
    float* out = (float*)d_out;

    __half *xt, *wq, *wkv, *wo, *qt, *kv, *mt, *pp, *yp;
    float *bkv, *mean, *istd;
    cudaGetSymbolAddress((void**)&xt,  g_xt);
    cudaGetSymbolAddress((void**)&wq,  g_wq);
    cudaGetSymbolAddress((void**)&wkv, g_wkv);
    cudaGetSymbolAddress((void**)&wo,  g_wo);
    cudaGetSymbolAddress((void**)&qt,  g_qt);
    cudaGetSymbolAddress((void**)&kv,  g_kv);
    cudaGetSymbolAddress((void**)&mt,  g_mt);
    cudaGetSymbolAddress((void**)&pp,  g_p);
    cudaGetSymbolAddress((void**)&yp,  g_y);
    cudaGetSymbolAddress((void**)&bkv, g_bkv);
    cudaGetSymbolAddress((void**)&mean, g_mean);
    cudaGetSymbolAddress((void**)&istd, g_istd);

    cudaFuncSetAttribute(wgemm<1, 3>, cudaFuncAttributeMaxDynamicSharedMemorySize, SMEM_B);
    cudaFuncSetAttribute(wgemm<2, 1>, cudaFuncAttributeMaxDynamicSharedMemorySize, SMEM_B);
    cudaFuncSetAttribute(wgemm<0, 1>, cudaFuncAttributeMaxDynamicSharedMemorySize, SMEM_B);
    cudaFuncSetAttribute(wgemm<1, 1>, cudaFuncAttributeMaxDynamicSharedMemorySize, SMEM_B);

    // conversions
    xtrans<<<dim3(Tn / 32, Cn / 32, Bn), 256>>>(x, xt);
    const size_t nw4 = (size_t)Dn * Cn / 4;   // per weight tensor
    wconv4<<<dim3((unsigned)((nw4 + 255) / 256), 4), 256>>>(
        Wk, Wv, Wq, Wo, wkv, wkv + (size_t)Dn * Cn, wq, wo, nw4);
    packbias<<<4, 256>>>(bk, bv, bkv);

    const size_t sTC  = (size_t)Tn * Cn;
    const size_t sTD  = (size_t)Tn * Dn;
    const size_t s2DS = (size_t)2 * Dn * Sn;
    const size_t sDD  = (size_t)Dn * Dn;
    const size_t sCD  = (size_t)Cn * Dn;
    const size_t sCT  = (size_t)Cn * Tn;

    // KV proj + fused pool: [Kp;Vp](2D,S) = pool2(Wkv x + bkv)
    const dim3 gkv(Tn / 128, 2 * Dn / 128, Bn);
    wgemm<1, 3><<<gkv, 256, SMEM_B>>>(wkv, xt, bkv, kv, 2 * Dn, Tn, Cn, 1.f, 0, sTC, s2DS);

    // Q^T(T,D) = xT Wq^T + bq(col)
    const dim3 gq(Dn / 128, Tn / 128, Bn);
    wgemm<2, 1><<<gq, 256, SMEM_B>>>(xt, wq, bq, qt, Tn, Dn, Cn, 1.f, sTC, 0, sTD);

    // Mt(D,D) = Kp Vp^T  (= M^T)
    const dim3 gm(Dn / 128, Dn / 128, Bn);
    wgemm<0, 1><<<gm, 256, SMEM_B>>>(kv, kv + (size_t)Dn * Sn, nullptr, mt,
                                     Dn, Dn, Sn, 1.f, s2DS, s2DS, sDD);

    // P(C,D) = Wo M = Wo Mt^T
    const dim3 gp(Dn / 128, Cn / 128, Bn);
    wgemm<0, 1><<<gp, 256, SMEM_B>>>(wo, mt, nullptr, pp, Cn, Dn, Dn, 1.f, 0, sDD, sCD);

    // y(C,T) = (1/T) P Q + bo
    const dim3 gy(Tn / 128, Cn / 128, Bn);
    wgemm<1, 1><<<gy, 256, SMEM_B>>>(pp, qt, bo, yp, Cn, Tn, Dn, 1.f / (float)Tn,
                                     sCD, sTD, sCT);

    // BatchNorm + residual
    bn_stats<<<Cn, 256>>>(yp, mean, istd);
    const size_t total4 = (size_t)Bn * Cn * Tn / 4;
    bn_apply<<<(unsigned)((total4 + 255) / 256), 256>>>(yp, x, mean, istd, gamma, beta, out);
}

// round 8
// speedup vs baseline: 6.2404x; 1.0773x over previous
#include <cuda_runtime.h>
#include <cuda_fp16.h>

#define Bn 16
#define Cn 1024
#define Tn 2048
#define Dn 512
#define Sn (Tn / 2)
#define EPSf 1e-5f

typedef unsigned int u32;

// ---------------- scratch (static device arrays) ----------------
__device__ __align__(16) __half g_xt [(size_t)Bn * Tn * Cn];        // x^T (B,T,C)
__device__ __align__(16) __half g_wq [Dn * Cn];
__device__ __align__(16) __half g_wkv[2 * Dn * Cn];                 // [Wk; Wv] stacked
__device__ __align__(16) __half g_wo [Cn * Dn];
__device__ __align__(16) __half g_qt [(size_t)Bn * Tn * Dn];        // Q^T (B,T,D)
__device__ __align__(16) __half g_kv [(size_t)Bn * 2 * Dn * Sn];    // [Kp; Vp] pooled (B,2D,S)
__device__ __align__(16) __half g_mt [(size_t)Bn * Dn * Dn];        // Mt = Kp Vp^T
__device__ __align__(16) __half g_p  [(size_t)Bn * Cn * Dn];        // P = Wo M
__device__ __align__(16) __half g_y  [(size_t)Bn * Cn * Tn];        // pre-BN y (fp16)
__device__ float g_bkv[2 * Dn];
__device__ float g_mean[Cn];
__device__ float g_istd[Cn];

// ---------------- PTX helpers ----------------
__device__ __forceinline__ u32 smem_u32(const void* p) {
    u32 a;
    asm("{ .reg .u64 t; cvta.to.shared.u64 t, %1; cvt.u32.u64 %0, t; }" : "=r"(a) : "l"(p));
    return a;
}

#define CPA16(dst, src) \
    asm volatile("cp.async.cg.shared.global [%0], [%1], 16;" :: "r"(dst), "l"(src) : "memory")
#define CP_COMMIT() asm volatile("cp.async.commit_group;" ::: "memory")

#define LDSM4(r, a) \
    asm volatile("ldmatrix.sync.aligned.m8n8.x4.shared.b16 {%0,%1,%2,%3}, [%4];" \
        : "=r"((r)[0]), "=r"((r)[1]), "=r"((r)[2]), "=r"((r)[3]) : "r"(a))

#define MMA_F16(d, a, b0, b1) \
    asm volatile("mma.sync.aligned.m16n8k16.row.col.f32.f16.f16.f32 " \
        "{%0,%1,%2,%3}, {%4,%5,%6,%7}, {%8,%9}, {%0,%1,%2,%3};" \
        : "+f"((d)[0]), "+f"((d)[1]), "+f"((d)[2]), "+f"((d)[3]) \
        : "r"((a)[0]), "r"((a)[1]), "r"((a)[2]), "r"((a)[3]), "r"(b0), "r"(b1))

__device__ __forceinline__ u32 pack_h2(float v0, float v1) {
    __half h0 = __float2half_rn(v0), h1 = __float2half_rn(v1);
    return (u32)__half_as_ushort(h0) | ((u32)__half_as_ushort(h1) << 16);
}

// ---------------- warp-MMA plain-fp16 GEMM, 4-stage pipeline ----------------
// C(M,N) = alpha * A(M,K) * Bt(N,K)^T + bias
// A, Bt row-major K-major fp16; fp32 accumulate. Requires K % 128 == 0.
// BIAS: 0 none, 1 per-row, 2 per-col.
// OMODE: 1 fp16; 3 pool2 along N -> fp16 (N halves).
// CTA 128x128, BK=32, 8 warps (32x64), cp.async 4-stage pipeline,
// precomputed streaming pointers (no per-iter IMAD storm),
// compile-time buffer indices via 4x inner unroll,
// 80B-padded smem rows (conflict-free ldmatrix).
#define TILE_B 10240           // 128 rows * 80 B
#define BUF_B  (2 * TILE_B)    // A, B
#define SMEM_B (4 * BUF_B)     // 4-stage = 81920

template <int BIAS, int OMODE>
__global__ void __launch_bounds__(256, 2) wgemm(
    const __half* __restrict__ A, const __half* __restrict__ Bt,
    const float* __restrict__ bias,
    __half* __restrict__ Ch,
    int M, int N, int K, float alpha,
    size_t sA, size_t sB, size_t sC)
{
    extern __shared__ __align__(128) char smem[];
    const u32 sbase = smem_u32(smem);
    const int tid = threadIdx.x;
    const int lane = tid & 31;
    const int warp = tid >> 5;
    const int wr = warp >> 1;       // 0..3 -> 32-row block
    const int wc = warp & 1;        // 0..1 -> 64-col block

    A  += (size_t)blockIdx.z * sA;
    Bt += (size_t)blockIdx.z * sB;
    const size_t coff = (size_t)blockIdx.z * sC;

    const int brow = blockIdx.y * 128;
    const int bcol = blockIdx.x * 128;
    const int KT = K >> 5;          // number of BK=32 steps (multiple of 4)

    // ---- streaming load pointers (computed once) ----
    const int rA = tid >> 2;              // 0..63
    const int cA = (tid & 3) * 8;         // 0,8,16,24 halfs
    const __half* pA = A  + (size_t)(brow + rA) * K + cA;
    const __half* pB = Bt + (size_t)(bcol + rA) * K + cA;
    const size_t rskip = (size_t)64 * K;  // second 64-row group
    const u32 dA = sbase + (u32)(rA * 80 + (tid & 3) * 16);
    const u32 dB = dA + TILE_B;

    auto load_at = [&](u32 bufoff, const __half* a, const __half* b) {
        CPA16(dA + bufoff, a);
        CPA16(dA + bufoff + 64u * 80u, a + rskip);
        CPA16(dB + bufoff, b);
        CPA16(dB + bufoff + 64u * 80u, b + rskip);
    };

    float acc[2][8][4];
#pragma unroll
    for (int i = 0; i < 2; i++)
#pragma unroll
        for (int j = 0; j < 8; j++)
#pragma unroll
            for (int q = 0; q < 4; q++) acc[i][j][q] = 0.f;

    // ---- 4-stage prologue: load k-tiles 0,1,2 ----
    load_at(0,         pA,      pB);      CP_COMMIT();
    load_at(BUF_B,     pA + 32, pB + 32); CP_COMMIT();
    load_at(2 * BUF_B, pA + 64, pB + 64); CP_COMMIT();
    const __half* qA = pA + 96;
    const __half* qB = pB + 96;

    const u32 rowoff = (u32)(((lane >> 3) & 1) * 8 + (lane & 7));
    const u32 chsel  = (u32)(lane >> 4);
    const u32 aoff = (u32)(wr * 32 + rowoff) * 80 + chsel * 16;
    const u32 boff = TILE_B + (u32)(wc * 64 + rowoff) * 80 + chsel * 16;

    for (int kt0 = 0; kt0 < KT; kt0 += 4) {
#pragma unroll
        for (int u = 0; u < 4; u++) {
            const int kt = kt0 + u;
            asm volatile("cp.async.wait_group 2;" ::: "memory");
            __syncthreads();   // tile kt visible; buffer (kt+3)&3 reusable

            if (kt + 3 < KT) {
                load_at((u32)(((u + 3) & 3)) * BUF_B, qA, qB);
                qA += 32; qB += 32;
            }
            CP_COMMIT();       // commit every iter to keep group counts aligned

            const u32 at = sbase + (u32)u * BUF_B;
#pragma unroll
            for (int ks = 0; ks < 2; ks++) {
                const u32 choff = (u32)ks * 32;
                u32 ar[2][4];
#pragma unroll
                for (int i = 0; i < 2; i++)
                    LDSM4(ar[i], at + aoff + (u32)i * (16 * 80) + choff);
                u32 br[4][4];
#pragma unroll
                for (int j4 = 0; j4 < 4; j4++)
                    LDSM4(br[j4], at + boff + (u32)j4 * (16 * 80) + choff);
#pragma unroll
                for (int i = 0; i < 2; i++)
#pragma unroll
                    for (int j = 0; j < 8; j++) {
                        const int j4 = j >> 1, h = j & 1;
                        MMA_F16(acc[i][j], ar[i], br[j4][h], br[j4][h + 2]);
                    }
            }
        }
    }

    // ---------------- epilogue ----------------
    const int r0 = brow + wr * 32 + (lane >> 2);
    const int c0l = wc * 64 + (lane & 3) * 2;
#pragma unroll
    for (int i = 0; i < 2; i++) {
#pragma unroll
        for (int half = 0; half < 2; half++) {
            const int row = r0 + i * 16 + half * 8;
            const float badd = (BIAS == 1) ? bias[row] : 0.f;
#pragma unroll
            for (int j = 0; j < 8; j++) {
                const int col = bcol + c0l + j * 8;
                float v0 = alpha * acc[i][j][half * 2 + 0] + badd;
                float v1 = alpha * acc[i][j][half * 2 + 1] + badd;
                if (BIAS == 2) { v0 += bias[col]; v1 += bias[col + 1]; }
                if (OMODE == 1) {
                    *(u32*)(Ch + coff + (size_t)row * N + col) = pack_h2(v0, v1);
                } else { // OMODE == 3: maxpool pairs of adjacent cols
                    Ch[coff + (size_t)row * (N >> 1) + (col >> 1)] =
                        __float2half_rn(fmaxf(v0, v1));
                }
            }
        }
    }
}

// ---------------- x (B,C,T) fp32 -> x^T (B,T,C) fp16 ----------------
__global__ void xtrans(const float* __restrict__ x, __half* __restrict__ o)
{
    __shared__ float s[32][33];
    const int b = blockIdx.z;
    const int c0 = blockIdx.y * 32;
    const int t0 = blockIdx.x * 32;
    const int tid = threadIdx.x;
    for (int i = tid; i < 1024; i += 256) {
        const int r = i >> 5, cc = i & 31;
        s[r][cc] = x[((size_t)b * Cn + c0 + r) * Tn + t0 + cc];
    }
    __syncthreads();
    for (int i = tid; i < 512; i += 256) {
        const int r = i >> 4, cp = (i & 15) * 2;
        const size_t oo = ((size_t)b * Tn + t0 + r) * Cn + c0 + cp;
        *(u32*)(o + oo) = pack_h2(s[cp][r], s[cp + 1][r]);
    }
}

// ---------------- 4x weight fp32 -> fp16 (one launch) ----------------
__global__ void wconv4(const float* __restrict__ w0, const float* __restrict__ w1,
                       const float* __restrict__ w2, const float* __restrict__ w3,
                       __half* __restrict__ o0, __half* __restrict__ o1,
                       __half* __restrict__ o2, __half* __restrict__ o3, size_t n4)
{
    const size_t i = (size_t)blockIdx.x * blockDim.x + threadIdx.x;
    if (i >= n4) return;
    const float* srcs[4] = {w0, w1, w2, w3};
    __half* dsts[4] = {o0, o1, o2, o3};
    const float4 v = ((const float4*)srcs[blockIdx.y])[i];
    ((uint2*)dsts[blockIdx.y])[i] = make_uint2(pack_h2(v.x, v.y), pack_h2(v.z, v.w));
}

// ---------------- stack bk|bv into one bias vector ----------------
__global__ void packbias(const float* __restrict__ bk, const float* __restrict__ bv,
                         float* __restrict__ o)
{
    const int i = blockIdx.x * blockDim.x + threadIdx.x;
    if (i < Dn) o[i] = bk[i];
    else if (i < 2 * Dn) o[i] = bv[i - Dn];
}

// ---------------- BN batch stats (fp16 y) ----------------
__global__ void bn_stats(const __half* __restrict__ y,
                         float* __restrict__ mean, float* __restrict__ istd)
{
    const int c = blockIdx.x;
    float s = 0.f, s2 = 0.f;
    for (int b = 0; b < Bn; b++) {
        const __half* row = y + ((size_t)b * Cn + c) * Tn;
        for (int t = threadIdx.x * 8; t < Tn; t += blockDim.x * 8) {
            const uint4 u = *(const uint4*)(row + t);
            const u32 w[4] = {u.x, u.y, u.z, u.w};
#pragma unroll
            for (int q = 0; q < 4; q++) {
                const float2 f = __half22float2(*(const __half2*)&w[q]);
                s  += f.x + f.y;
                s2 += f.x * f.x + f.y * f.y;
            }
        }
    }
#pragma unroll
    for (int o = 16; o > 0; o >>= 1) {
        s  += __shfl_down_sync(0xffffffffu, s,  o);
        s2 += __shfl_down_sync(0xffffffffu, s2, o);
    }
    __shared__ float ss[32], ss2[32];
    const int lane = threadIdx.x & 31, w = threadIdx.x >> 5;
    if (lane == 0) { ss[w] = s; ss2[w] = s2; }
    __syncthreads();
    if (w == 0) {
        const int nw = blockDim.x >> 5;
        s  = lane < nw ? ss[lane]  : 0.f;
        s2 = lane < nw ? ss2[lane] : 0.f;
#pragma unroll
        for (int o = 16; o > 0; o >>= 1) {
            s  += __shfl_down_sync(0xffffffffu, s,  o);
            s2 += __shfl_down_sync(0xffffffffu, s2, o);
        }
        if (lane == 0) {
            const float n = (float)(Bn * Tn);
            const float m = s / n;
            mean[c] = m;
            istd[c] = rsqrtf(s2 / n - m * m + EPSf);
        }
    }
}

// ---------------- BN apply + residual ----------------
__global__ void bn_apply(const __half* __restrict__ y, const float* __restrict__ x,
                         const float* __restrict__ mean, const float* __restrict__ istd,
                         const float* __restrict__ gamma, const float* __restrict__ beta,
                         float* __restrict__ out)
{
    const size_t i4 = ((size_t)blockIdx.x * blockDim.x + threadIdx.x) * 4;
    const size_t total = (size_t)Bn * Cn * Tn;
    if (i4 >= total) return;
    const int c = (int)((i4 / Tn) % Cn);
    const float g = gamma[c] * istd[c];
    const float m = mean[c];
    const float bt = beta[c];
    const uint2 u = *(const uint2*)(y + i4);
    const float2 f0 = __half22float2(*(const __half2*)&u.x);
    const float2 f1 = __half22float2(*(const __half2*)&u.y);
    const float4 xv = *(const float4*)(x + i4);
    float4 o;
    o.x = g * (f0.x - m) + bt + xv.x;
    o.y = g * (f0.y - m) + bt + xv.y;
    o.z = g * (f1.x - m) + bt + xv.z;
    o.w = g * (f1.y - m) + bt + xv.w;
    *(float4*)(out + i4) = o;
}

extern "C" void kernel_launch(void* const* d_in, const int* in_sizes, int n_in,
                              void* d_out, int out_size)
{
    const float* x     = (const float*)d_in[0];
    const float* Wq    = (const float*)d_in[1];
    const float* bq    = (const float*)d_in[2];
    const float* Wk    = (const float*)d_in[3];
    const float* bk    = (const float*)d_in[4];
    const float* Wv    = (const float*)d_in[5];
    const float* bv    = (const float*)d_in[6];
    const float* Wo    = (const float*)d_in[7];
    const float* bo    = (const float*)d_in[8];
    const float* gamma = (const float*)d_in[9];
    const float* beta  = (const float*)d_in[10];
    float* out = (float*)d_out;

    __half *xt, *wq, *wkv, *wo, *qt, *kv, *mt, *pp, *yp;
    float *bkv, *mean, *istd;
    cudaGetSymbolAddress((void**)&xt,  g_xt);
    cudaGetSymbolAddress((void**)&wq,  g_wq);
    cudaGetSymbolAddress((void**)&wkv, g_wkv);
    cudaGetSymbolAddress((void**)&wo,  g_wo);
    cudaGetSymbolAddress((void**)&qt,  g_qt);
    cudaGetSymbolAddress((void**)&kv,  g_kv);
    cudaGetSymbolAddress((void**)&mt,  g_mt);
    cudaGetSymbolAddress((void**)&pp,  g_p);
    cudaGetSymbolAddress((void**)&yp,  g_y);
    cudaGetSymbolAddress((void**)&bkv, g_bkv);
    cudaGetSymbolAddress((void**)&mean, g_mean);
    cudaGetSymbolAddress((void**)&istd, g_istd);

    cudaFuncSetAttribute(wgemm<1, 3>, cudaFuncAttributeMaxDynamicSharedMemorySize, SMEM_B);
    cudaFuncSetAttribute(wgemm<2, 1>, cudaFuncAttributeMaxDynamicSharedMemorySize, SMEM_B);
    cudaFuncSetAttribute(wgemm<0, 1>, cudaFuncAttributeMaxDynamicSharedMemorySize, SMEM_B);
    cudaFuncSetAttribute(wgemm<1, 1>, cudaFuncAttributeMaxDynamicSharedMemorySize, SMEM_B);

    // conversions
    xtrans<<<dim3(Tn / 32, Cn / 32, Bn), 256>>>(x, xt);
    const size_t nw4 = (size_t)Dn * Cn / 4;   // per weight tensor
    wconv4<<<dim3((unsigned)((nw4 + 255) / 256), 4), 256>>>(
        Wk, Wv, Wq, Wo, wkv, wkv + (size_t)Dn * Cn, wq, wo, nw4);
    packbias<<<4, 256>>>(bk, bv, bkv);

    const size_t sTC  = (size_t)Tn * Cn;
    const size_t sTD  = (size_t)Tn * Dn;
    const size_t s2DS = (size_t)2 * Dn * Sn;
    const size_t sDD  = (size_t)Dn * Dn;
    const size_t sCD  = (size_t)Cn * Dn;
    const size_t sCT  = (size_t)Cn * Tn;

    // KV proj + fused pool: [Kp;Vp](2D,S) = pool2(Wkv x + bkv)
    const dim3 gkv(Tn / 128, 2 * Dn / 128, Bn);
    wgemm<1, 3><<<gkv, 256, SMEM_B>>>(wkv, xt, bkv, kv, 2 * Dn, Tn, Cn, 1.f, 0, sTC, s2DS);

    // Q^T(T,D) = xT Wq^T + bq(col)
    const dim3 gq(Dn / 128, Tn / 128, Bn);
    wgemm<2, 1><<<gq, 256, SMEM_B>>>(xt, wq, bq, qt, Tn, Dn, Cn, 1.f, sTC, 0, sTD);

    // Mt(D,D) = Kp Vp^T  (= M^T)
    const dim3 gm(Dn / 128, Dn / 128, Bn);
    wgemm<0, 1><<<gm, 256, SMEM_B>>>(kv, kv + (size_t)Dn * Sn, nullptr, mt,
                                     Dn, Dn, Sn, 1.f, s2DS, s2DS, sDD);

    // P(C,D) = Wo M = Wo Mt^T
    const dim3 gp(Dn / 128, Cn / 128, Bn);
    wgemm<0, 1><<<gp, 256, SMEM_B>>>(wo, mt, nullptr, pp, Cn, Dn, Dn, 1.f, 0, sDD, sCD);

    // y(C,T) = (1/T) P Q + bo
    const dim3 gy(Tn / 128, Cn / 128, Bn);
    wgemm<1, 1><<<gy, 256, SMEM_B>>>(pp, qt, bo, yp, Cn, Tn, Dn, 1.f / (float)Tn,
                                     sCD, sTD, sCT);

    // BatchNorm + residual
    bn_stats<<<Cn, 256>>>(yp, mean, istd);
    const size_t total4 = (size_t)Bn * Cn * Tn / 4;
    bn_apply<<<(unsigned)((total4 + 255) / 256), 256>>>(yp, x, mean, istd, gamma, beta, out);
}